// round 5
// baseline (speedup 1.0000x reference)
#include <cuda_runtime.h>
#include <math.h>

#define NN 4096
#define MM 8192
#define DD 512
#define N_ITERS 200
#define LOGA   (-8.317766166719343f)   // -log(4096)
#define FR 16                          // rows per fused block
#define NCHUNK (NN / FR)               // 256 partial chunks
#define CHUNKS 64                      // for k_ot only
#define LN2F    0.69314718055994531f
#define LOG2EF  1.44269504088896340f

// ---------------- device scratch ----------------
__device__ __align__(16) unsigned short d_Cq[(size_t)NN * MM];  // u16 quantized cost (64MB)
__device__ __align__(16) float d_f[NN];      // nat potentials
__device__ __align__(16) float d_g[MM];
__device__ __align__(16) float d_g2[MM];     // staged base-2 shifted potentials
__device__ __align__(16) float d_logb[MM];
__device__ __align__(16) float d_xsq[NN];
__device__ __align__(16) float d_ysq[MM];
__device__ __align__(16) float d_pm[(size_t)NCHUNK * MM];   // 8 MB
__device__ __align__(16) float d_ps[(size_t)NCHUNK * MM];   // 8 MB
__device__ double d_ot;
__device__ double d_sq;
__device__ double d_cnt;
__device__ int    d_is64;
__device__ float d_qK2, d_fgC, d_step, d_invstep, d_qdqB;

__device__ __forceinline__ float ex2(float x) {
    float r; asm("ex2.approx.ftz.f32 %0, %1;" : "=f"(r) : "f"(x)); return r;
}
__device__ __forceinline__ float lg2(float x) {
    float r; asm("lg2.approx.ftz.f32 %0, %1;" : "=f"(r) : "f"(x)); return r;
}
// u16 -> float(2^23 + q), one PRMT
__device__ __forceinline__ float qf_lo(unsigned w) {
    return __uint_as_float(__byte_perm(w, 0x4B000000u, 0x7410));
}
__device__ __forceinline__ float qf_hi(unsigned w) {
    return __uint_as_float(__byte_perm(w, 0x4B000000u, 0x7432));
}

// ---------------- init ----------------
__global__ void k_init(const float* __restrict__ tgt, const int* __restrict__ al_raw) {
    __shared__ float red[32];
    __shared__ float s_total;
    int t = threadIdx.x;
    float s = 0.f;
    for (int j = t; j < MM; j += 1024) s += tgt[j];
    #pragma unroll
    for (int o = 16; o; o >>= 1) s += __shfl_down_sync(0xffffffffu, s, o);
    if ((t & 31) == 0) red[t >> 5] = s;
    __syncthreads();
    if (t < 32) {
        float v = red[t];
        #pragma unroll
        for (int o = 16; o; o >>= 1) v += __shfl_down_sync(0xffffffffu, v, o);
        if (t == 0) s_total = v;
    }
    __syncthreads();
    float lt = logf(s_total);
    for (int j = t; j < MM; j += 1024) {
        d_logb[j] = logf(tgt[j]) - lt;
        d_g[j] = 0.f;
    }
    int odd_nz = 0;
    for (int i = t; i < NN / 2; i += 1024)
        if (al_raw[2 * i + 1] != 0) odd_nz = 1;
    odd_nz = __syncthreads_or(odd_nz);
    if (t == 0) {
        d_is64 = odd_nz ? 0 : 1;
        d_ot = 0.0; d_sq = 0.0; d_cnt = 0.0;
    }
}

// ---------------- row squared norms ----------------
__global__ __launch_bounds__(128) void k_sqnorm(const float* __restrict__ X, int which) {
    int row = blockIdx.x, t = threadIdx.x;
    float4 v = ((const float4*)X)[(size_t)row * (DD / 4) + t];
    float s = v.x * v.x + v.y * v.y + v.z * v.z + v.w * v.w;
    #pragma unroll
    for (int o = 16; o; o >>= 1) s += __shfl_down_sync(0xffffffffu, s, o);
    __shared__ float red[4];
    if ((t & 31) == 0) red[t >> 5] = s;
    __syncthreads();
    if (t == 0) {
        float tot = red[0] + red[1] + red[2] + red[3];
        if (which == 0) d_xsq[row] = tot; else d_ysq[row] = tot;
    }
}

// ---------------- quantizer constants from norm bounds (C in [0, B]) ----------------
__global__ void k_scale() {
    __shared__ float red[32];
    int t = threadIdx.x;
    float mx = 0.f;
    for (int i = t; i < NN; i += 1024) mx = fmaxf(mx, d_xsq[i]);
    #pragma unroll
    for (int o = 16; o; o >>= 1) mx = fmaxf(mx, __shfl_xor_sync(0xffffffffu, mx, o));
    if ((t & 31) == 0) red[t >> 5] = mx;
    __syncthreads();
    float my = 0.f;
    for (int i = t; i < MM; i += 1024) my = fmaxf(my, d_ysq[i]);
    #pragma unroll
    for (int o = 16; o; o >>= 1) my = fmaxf(my, __shfl_xor_sync(0xffffffffu, my, o));
    __shared__ float red2[32];
    if ((t & 31) == 0) red2[t >> 5] = my;
    __syncthreads();
    if (t == 0) {
        float MX = 0.f, MY = 0.f;
        #pragma unroll
        for (int k = 0; k < 32; k++) { MX = fmaxf(MX, red[k]); MY = fmaxf(MY, red2[k]); }
        double B = 1.02 * ((double)sqrtf(MX) + (double)sqrtf(MY)) + 1e-3;
        double st = B / 65535.0;
        const double L2E = 1.4426950408889634;
        float K2f = (float)(10.0 * st * L2E);
        d_step = (float)st;
        d_invstep = (float)(1.0 / st);
        d_qK2 = K2f;
        d_fgC = (float)(8388608.0 * (double)K2f);   // 2^23*K2 fold for magic dequant
        d_qdqB = (float)(-8388608.0 * st);
    }
}

// ---------------- GEMM + cdist epilogue, writes u16 directly ----------------
__global__ __launch_bounds__(256) void k_gemm(const float* __restrict__ X, const float* __restrict__ Y) {
    __shared__ float As[16][128];
    __shared__ float Bs[16][128];
    int tid = threadIdx.x;
    int bx = blockIdx.x, by = blockIdx.y;
    int tx = tid & 15, ty = tid >> 4;
    float acc[8][8];
    #pragma unroll
    for (int i = 0; i < 8; i++)
        #pragma unroll
        for (int j = 0; j < 8; j++) acc[i][j] = 0.f;

    const float* Xb = X + (size_t)by * 128 * DD;
    const float* Yb = Y + (size_t)bx * 128 * DD;

    for (int kt = 0; kt < DD; kt += 16) {
        __syncthreads();
        #pragma unroll
        for (int i = 0; i < 2; i++) {
            int l  = tid + i * 256;
            int r  = l >> 2;
            int c4 = l & 3;
            float4 va = *(const float4*)(Xb + (size_t)r * DD + kt + c4 * 4);
            As[c4 * 4 + 0][r] = va.x; As[c4 * 4 + 1][r] = va.y;
            As[c4 * 4 + 2][r] = va.z; As[c4 * 4 + 3][r] = va.w;
            float4 vb = *(const float4*)(Yb + (size_t)r * DD + kt + c4 * 4);
            Bs[c4 * 4 + 0][r] = vb.x; Bs[c4 * 4 + 1][r] = vb.y;
            Bs[c4 * 4 + 2][r] = vb.z; Bs[c4 * 4 + 3][r] = vb.w;
        }
        __syncthreads();
        #pragma unroll
        for (int kk = 0; kk < 16; kk++) {
            float a[8], b[8];
            *(float4*)(a)     = *(const float4*)&As[kk][ty * 8];
            *(float4*)(a + 4) = *(const float4*)&As[kk][ty * 8 + 4];
            *(float4*)(b)     = *(const float4*)&Bs[kk][tx * 8];
            *(float4*)(b + 4) = *(const float4*)&Bs[kk][tx * 8 + 4];
            #pragma unroll
            for (int i = 0; i < 8; i++)
                #pragma unroll
                for (int j = 0; j < 8; j++)
                    acc[i][j] = fmaf(a[i], b[j], acc[i][j]);
        }
    }
    int i0 = by * 128 + ty * 8;
    int j0 = bx * 128 + tx * 8;
    float inv = d_invstep;
    float ys[8];
    #pragma unroll
    for (int jj = 0; jj < 8; jj++) ys[jj] = d_ysq[j0 + jj];
    #pragma unroll
    for (int ii = 0; ii < 8; ii++) {
        float xs = d_xsq[i0 + ii];
        unsigned q[8];
        #pragma unroll
        for (int jj = 0; jj < 8; jj++) {
            float sq = xs + ys[jj] - 2.0f * acc[ii][jj];
            float c = sqrtf(fmaxf(sq, 1e-12f));
            unsigned qq = __float2uint_rn(c * inv);
            q[jj] = qq > 65535u ? 65535u : qq;
        }
        uint4 o;
        o.x = __byte_perm(q[0], q[1], 0x5410);
        o.y = __byte_perm(q[2], q[3], 0x5410);
        o.z = __byte_perm(q[4], q[5], 0x5410);
        o.w = __byte_perm(q[6], q[7], 0x5410);
        *(uint4*)(d_Cq + (size_t)(i0 + ii) * MM + j0) = o;
    }
}

// ---------------- g2 init (g=0) ----------------
__global__ void k_ginit() {
    d_g2[blockIdx.x * 256 + threadIdx.x] = d_fgC;
}

// ---------------- FUSED: f update (row LSE) + column partial accumulation ----------------
// One read of C per iteration; exp2 values reused for both updates.
__global__ __launch_bounds__(256, 2) void k_fused() {
    __shared__ float wm[FR][8], ws[FR][8];
    __shared__ float bF2[FR];
    int t = threadIdx.x, lane = t & 31, w = t >> 5;
    float K2 = d_qK2, fgC = d_fgC;
    int row0 = blockIdx.x * FR;

    // this thread's 32 g2 values (columns {(s*256+t)*8 + e})
    float g2r[32];
    #pragma unroll
    for (int s = 0; s < 4; s++) {
        float4 a = *(const float4*)(d_g2 + (size_t)(s * 256 + t) * 8);
        float4 b = *(const float4*)(d_g2 + (size_t)(s * 256 + t) * 8 + 4);
        g2r[s * 8 + 0] = a.x; g2r[s * 8 + 1] = a.y; g2r[s * 8 + 2] = a.z; g2r[s * 8 + 3] = a.w;
        g2r[s * 8 + 4] = b.x; g2r[s * 8 + 5] = b.y; g2r[s * 8 + 6] = b.z; g2r[s * 8 + 7] = b.w;
    }

    float acc[32];
    #pragma unroll
    for (int j = 0; j < 32; j++) acc[j] = 0.f;
    float St = -1e30f;

    for (int rr = 0; rr < FR; rr++) {
        const uint4* Crow = (const uint4*)(d_Cq + (size_t)(row0 + rr) * MM);
        float e[32];
        #pragma unroll
        for (int s = 0; s < 4; s++) {
            uint4 cv = Crow[s * 256 + t];
            e[s * 8 + 0] = fmaf(qf_lo(cv.x), -K2, g2r[s * 8 + 0]);
            e[s * 8 + 1] = fmaf(qf_hi(cv.x), -K2, g2r[s * 8 + 1]);
            e[s * 8 + 2] = fmaf(qf_lo(cv.y), -K2, g2r[s * 8 + 2]);
            e[s * 8 + 3] = fmaf(qf_hi(cv.y), -K2, g2r[s * 8 + 3]);
            e[s * 8 + 4] = fmaf(qf_lo(cv.z), -K2, g2r[s * 8 + 4]);
            e[s * 8 + 5] = fmaf(qf_hi(cv.z), -K2, g2r[s * 8 + 5]);
            e[s * 8 + 6] = fmaf(qf_lo(cv.w), -K2, g2r[s * 8 + 6]);
            e[s * 8 + 7] = fmaf(qf_hi(cv.w), -K2, g2r[s * 8 + 7]);
        }
        float mt = e[0];
        #pragma unroll
        for (int i = 1; i < 32; i++) mt = fmaxf(mt, e[i]);
        float s0 = 0.f, s1 = 0.f, s2 = 0.f, s3 = 0.f;
        #pragma unroll
        for (int i = 0; i < 32; i += 4) {
            e[i + 0] = ex2(e[i + 0] - mt); s0 += e[i + 0];
            e[i + 1] = ex2(e[i + 1] - mt); s1 += e[i + 1];
            e[i + 2] = ex2(e[i + 2] - mt); s2 += e[i + 2];
            e[i + 3] = ex2(e[i + 3] - mt); s3 += e[i + 3];
        }
        float sloc = (s0 + s1) + (s2 + s3);

        // warp fixed-shift reduce
        float M = mt;
        #pragma unroll
        for (int o = 16; o; o >>= 1) M = fmaxf(M, __shfl_xor_sync(0xffffffffu, M, o));
        float sw = sloc * ex2(mt - M);
        #pragma unroll
        for (int o = 16; o; o >>= 1) sw += __shfl_xor_sync(0xffffffffu, sw, o);
        if (lane == 0) { wm[rr][w] = M; ws[rr][w] = sw; }
        __syncthreads();
        if (w == 0) {
            float Mc = (lane < 8) ? wm[rr][lane] : -1e30f;
            float Sc = (lane < 8) ? ws[rr][lane] : 0.f;
            float Mf = Mc;
            #pragma unroll
            for (int o = 4; o; o >>= 1) Mf = fmaxf(Mf, __shfl_xor_sync(0xffffffffu, Mf, o));
            Sc *= ex2(Mc - Mf);
            #pragma unroll
            for (int o = 4; o; o >>= 1) Sc += __shfl_xor_sync(0xffffffffu, Sc, o);
            if (lane == 0) {
                float l2row = Mf + lg2(Sc);            // log2 of row sum
                float f = LOGA - LN2F * l2row;
                d_f[row0 + rr] = f;
                bF2[rr] = fmaf(f, LOG2EF, fgC);        // f2 (base-2 shifted)
            }
        }
        __syncthreads();

        // accumulate column partials: acc_j += e_j * 2^(mt + f2 - St)
        float arg = mt + bF2[rr];
        if (arg > St) {
            float rs = ex2(St - arg);
            #pragma unroll
            for (int j = 0; j < 32; j++) acc[j] *= rs;
            St = arg;
        }
        float coeff = ex2(arg - St);
        #pragma unroll
        for (int j = 0; j < 32; j++) acc[j] = fmaf(e[j], coeff, acc[j]);
    }

    // write partials: column LSE partial = (m = St - g2_j, s = acc_j)
    size_t base = (size_t)blockIdx.x * MM;
    #pragma unroll
    for (int s = 0; s < 4; s++) {
        int col = (s * 256 + t) * 8;
        float4 pa, pb;
        pa.x = St - g2r[s * 8 + 0]; pa.y = St - g2r[s * 8 + 1];
        pa.z = St - g2r[s * 8 + 2]; pa.w = St - g2r[s * 8 + 3];
        pb.x = St - g2r[s * 8 + 4]; pb.y = St - g2r[s * 8 + 5];
        pb.z = St - g2r[s * 8 + 6]; pb.w = St - g2r[s * 8 + 7];
        *(float4*)(d_pm + base + col)     = pa;
        *(float4*)(d_pm + base + col + 4) = pb;
        float4 sa, sb;
        sa.x = acc[s * 8 + 0]; sa.y = acc[s * 8 + 1]; sa.z = acc[s * 8 + 2]; sa.w = acc[s * 8 + 3];
        sb.x = acc[s * 8 + 4]; sb.y = acc[s * 8 + 5]; sb.z = acc[s * 8 + 6]; sb.w = acc[s * 8 + 7];
        *(float4*)(d_ps + base + col)     = sa;
        *(float4*)(d_ps + base + col + 4) = sb;
    }
}

// ---------------- g combine: two-pass max then sum over NCHUNK partials ----------------
__global__ __launch_bounds__(256) void k_gcomb() {
    int j = blockIdx.x * 256 + threadIdx.x;
    float M = -1e30f;
    #pragma unroll 8
    for (int c = 0; c < NCHUNK; c++)
        M = fmaxf(M, __ldg(&d_pm[(size_t)c * MM + j]));
    float S = 0.f;
    #pragma unroll 8
    for (int c = 0; c < NCHUNK; c++)
        S += __ldg(&d_ps[(size_t)c * MM + j]) * ex2(__ldg(&d_pm[(size_t)c * MM + j]) - M);
    float g = d_logb[j] - LN2F * (M + lg2(S));
    d_g[j] = g;
    d_g2[j] = fmaf(g, LOG2EF, d_fgC);
}

// ---------------- final OT loss ----------------
__global__ __launch_bounds__(256) void k_ot() {
    int t = threadIdx.x;
    int j = blockIdx.x * 1024 + t * 4;
    int r0 = blockIdx.y * (NN / CHUNKS);
    float K2 = d_qK2, stepf = d_step, qB = d_qdqB, fgC = d_fgC;
    float4 gv = *(const float4*)(d_g + j);
    float base[4];
    base[0] = fmaf(gv.x, LOG2EF, fgC);
    base[1] = fmaf(gv.y, LOG2EF, fgC);
    base[2] = fmaf(gv.z, LOG2EF, fgC);
    base[3] = fmaf(gv.w, LOG2EF, fgC);
    const unsigned short* Cb = d_Cq + j;
    float acc = 0.f;
    for (int r = r0; r < r0 + (NN / CHUNKS); r++) {
        float frl2 = __ldg(&d_f[r]) * LOG2EF;
        uint2 v = *(const uint2*)(Cb + (size_t)r * MM);
        float qf[4] = {qf_lo(v.x), qf_hi(v.x), qf_lo(v.y), qf_hi(v.y)};
        #pragma unroll
        for (int c = 0; c < 4; c++) {
            float p = ex2(fmaf(qf[c], -K2, base[c] + frl2));
            float cd = fmaf(qf[c], stepf, qB);
            acc = fmaf(p, cd, acc);
        }
    }
    double da = (double)acc;
    #pragma unroll
    for (int o = 16; o; o >>= 1) da += __shfl_down_sync(0xffffffffu, da, o);
    __shared__ double sd[8];
    int lane = t & 31, w = t >> 5;
    if (lane == 0) sd[w] = da;
    __syncthreads();
    if (t == 0) {
        double tot = 0.0;
        #pragma unroll
        for (int k = 0; k < 8; k++) tot += sd[k];
        atomicAdd(&d_ot, tot);
    }
}

// ---------------- supervised alignment MSE ----------------
__global__ __launch_bounds__(128) void k_dist(const float* __restrict__ X,
                                              const float* __restrict__ W,
                                              const int* __restrict__ al) {
    int row = blockIdx.x, t = threadIdx.x;
    long long idx; int mask;
    if (d_is64) {
        long long v = ((const long long*)al)[row];
        mask = (v != -1LL);
        idx = v < 0 ? 0 : v;
    } else {
        int v = al[row];
        mask = (v != -1);
        idx = v < 0 ? 0 : (long long)v;
    }
    float4 a = ((const float4*)X)[(size_t)row * (DD / 4) + t];
    float4 b = ((const float4*)W)[(size_t)idx * (DD / 4) + t];
    float dx = a.x - b.x, dy = a.y - b.y, dz = a.z - b.z, dw = a.w - b.w;
    float s = dx * dx + dy * dy + dz * dz + dw * dw;
    #pragma unroll
    for (int o = 16; o; o >>= 1) s += __shfl_down_sync(0xffffffffu, s, o);
    __shared__ float red[4];
    if ((t & 31) == 0) red[t >> 5] = s;
    __syncthreads();
    if (t == 0) {
        float tot = red[0] + red[1] + red[2] + red[3];
        if (mask) {
            atomicAdd(&d_sq, (double)tot);
            atomicAdd(&d_cnt, 1.0);
        }
    }
}

// ---------------- finalize ----------------
__global__ void k_final(float* out) {
    double dl = (d_cnt > 0.0) ? d_sq / (d_cnt * (double)DD) : 0.0;
    out[0] = (float)(d_ot + dl);
}

// ---------------- launch ----------------
extern "C" void kernel_launch(void* const* d_in, const int* in_sizes, int n_in,
                              void* d_out, int out_size) {
    const float* X  = (const float*)d_in[0];
    const float* W  = (const float*)d_in[1];
    const int*   AL = (const int*)d_in[2];
    const float* T  = (const float*)d_in[3];
    float* out = (float*)d_out;

    k_init<<<1, 1024>>>(T, AL);
    k_sqnorm<<<NN, 128>>>(X, 0);
    k_sqnorm<<<MM, 128>>>(W, 1);
    k_scale<<<1, 1024>>>();
    dim3 gg(MM / 128, NN / 128);
    k_gemm<<<gg, 256>>>(X, W);
    k_ginit<<<MM / 256, 256>>>();

    for (int it = 0; it < N_ITERS; it++) {
        k_fused<<<NN / FR, 256>>>();
        k_gcomb<<<MM / 256, 256>>>();
    }

    k_ot<<<dim3(8, CHUNKS), 256>>>();
    k_dist<<<NN, 128>>>(X, W, AL);
    k_final<<<1, 1>>>(out);
}

// round 6
// speedup vs baseline: 1.0751x; 1.0751x over previous
#include <cuda_runtime.h>
#include <math.h>

#define NN 4096
#define MM 8192
#define DD 512
#define N_ITERS 200
#define LOGA   (-8.317766166719343f)   // -log(4096)
#define FR 32                          // rows per fused block
#define NCHUNK (NN / FR)               // 128 partial chunks
#define CHUNKS 64                      // for k_ot only
#define LN2F    0.69314718055994531f
#define LOG2EF  1.44269504088896340f

// ---------------- device scratch ----------------
__device__ __align__(16) unsigned short d_Cq[(size_t)NN * MM];  // u16 quantized cost (64MB)
__device__ __align__(16) float d_f[NN];      // nat potentials
__device__ __align__(16) float d_g[MM];
__device__ __align__(16) float d_g2[MM];     // staged base-2 shifted potentials
__device__ __align__(16) float d_logb[MM];
__device__ __align__(16) float d_xsq[NN];
__device__ __align__(16) float d_ysq[MM];
__device__ __align__(16) float d_pm[(size_t)NCHUNK * MM];   // 4 MB
__device__ __align__(16) float d_ps[(size_t)NCHUNK * MM];   // 4 MB
__device__ double d_ot;
__device__ double d_sq;
__device__ double d_cnt;
__device__ int    d_is64;
__device__ float d_qK2, d_fgC, d_step, d_invstep, d_qdqB;

__device__ __forceinline__ float ex2(float x) {
    float r; asm("ex2.approx.ftz.f32 %0, %1;" : "=f"(r) : "f"(x)); return r;
}
__device__ __forceinline__ float lg2(float x) {
    float r; asm("lg2.approx.ftz.f32 %0, %1;" : "=f"(r) : "f"(x)); return r;
}
// u16 -> float(2^23 + q), one PRMT
__device__ __forceinline__ float qf_lo(unsigned w) {
    return __uint_as_float(__byte_perm(w, 0x4B000000u, 0x7410));
}
__device__ __forceinline__ float qf_hi(unsigned w) {
    return __uint_as_float(__byte_perm(w, 0x4B000000u, 0x7432));
}

// ---------------- init ----------------
__global__ void k_init(const float* __restrict__ tgt, const int* __restrict__ al_raw) {
    __shared__ float red[32];
    __shared__ float s_total;
    int t = threadIdx.x;
    float s = 0.f;
    for (int j = t; j < MM; j += 1024) s += tgt[j];
    #pragma unroll
    for (int o = 16; o; o >>= 1) s += __shfl_down_sync(0xffffffffu, s, o);
    if ((t & 31) == 0) red[t >> 5] = s;
    __syncthreads();
    if (t < 32) {
        float v = red[t];
        #pragma unroll
        for (int o = 16; o; o >>= 1) v += __shfl_down_sync(0xffffffffu, v, o);
        if (t == 0) s_total = v;
    }
    __syncthreads();
    float lt = logf(s_total);
    for (int j = t; j < MM; j += 1024) {
        d_logb[j] = logf(tgt[j]) - lt;
        d_g[j] = 0.f;
    }
    int odd_nz = 0;
    for (int i = t; i < NN / 2; i += 1024)
        if (al_raw[2 * i + 1] != 0) odd_nz = 1;
    odd_nz = __syncthreads_or(odd_nz);
    if (t == 0) {
        d_is64 = odd_nz ? 0 : 1;
        d_ot = 0.0; d_sq = 0.0; d_cnt = 0.0;
    }
}

// ---------------- row squared norms ----------------
__global__ __launch_bounds__(128) void k_sqnorm(const float* __restrict__ X, int which) {
    int row = blockIdx.x, t = threadIdx.x;
    float4 v = ((const float4*)X)[(size_t)row * (DD / 4) + t];
    float s = v.x * v.x + v.y * v.y + v.z * v.z + v.w * v.w;
    #pragma unroll
    for (int o = 16; o; o >>= 1) s += __shfl_down_sync(0xffffffffu, s, o);
    __shared__ float red[4];
    if ((t & 31) == 0) red[t >> 5] = s;
    __syncthreads();
    if (t == 0) {
        float tot = red[0] + red[1] + red[2] + red[3];
        if (which == 0) d_xsq[row] = tot; else d_ysq[row] = tot;
    }
}

// ---------------- quantizer constants from norm bounds (C in [0, B]) ----------------
__global__ void k_scale() {
    __shared__ float red[32];
    int t = threadIdx.x;
    float mx = 0.f;
    for (int i = t; i < NN; i += 1024) mx = fmaxf(mx, d_xsq[i]);
    #pragma unroll
    for (int o = 16; o; o >>= 1) mx = fmaxf(mx, __shfl_xor_sync(0xffffffffu, mx, o));
    if ((t & 31) == 0) red[t >> 5] = mx;
    __syncthreads();
    float my = 0.f;
    for (int i = t; i < MM; i += 1024) my = fmaxf(my, d_ysq[i]);
    #pragma unroll
    for (int o = 16; o; o >>= 1) my = fmaxf(my, __shfl_xor_sync(0xffffffffu, my, o));
    __shared__ float red2[32];
    if ((t & 31) == 0) red2[t >> 5] = my;
    __syncthreads();
    if (t == 0) {
        float MX = 0.f, MY = 0.f;
        #pragma unroll
        for (int k = 0; k < 32; k++) { MX = fmaxf(MX, red[k]); MY = fmaxf(MY, red2[k]); }
        double B = 1.02 * ((double)sqrtf(MX) + (double)sqrtf(MY)) + 1e-3;
        double st = B / 65535.0;
        const double L2E = 1.4426950408889634;
        float K2f = (float)(10.0 * st * L2E);
        d_step = (float)st;
        d_invstep = (float)(1.0 / st);
        d_qK2 = K2f;
        d_fgC = (float)(8388608.0 * (double)K2f);   // 2^23*K2 fold for magic dequant
        d_qdqB = (float)(-8388608.0 * st);
    }
}

// ---------------- GEMM + cdist epilogue, writes u16 directly ----------------
__global__ __launch_bounds__(256) void k_gemm(const float* __restrict__ X, const float* __restrict__ Y) {
    __shared__ float As[16][128];
    __shared__ float Bs[16][128];
    int tid = threadIdx.x;
    int bx = blockIdx.x, by = blockIdx.y;
    int tx = tid & 15, ty = tid >> 4;
    float acc[8][8];
    #pragma unroll
    for (int i = 0; i < 8; i++)
        #pragma unroll
        for (int j = 0; j < 8; j++) acc[i][j] = 0.f;

    const float* Xb = X + (size_t)by * 128 * DD;
    const float* Yb = Y + (size_t)bx * 128 * DD;

    for (int kt = 0; kt < DD; kt += 16) {
        __syncthreads();
        #pragma unroll
        for (int i = 0; i < 2; i++) {
            int l  = tid + i * 256;
            int r  = l >> 2;
            int c4 = l & 3;
            float4 va = *(const float4*)(Xb + (size_t)r * DD + kt + c4 * 4);
            As[c4 * 4 + 0][r] = va.x; As[c4 * 4 + 1][r] = va.y;
            As[c4 * 4 + 2][r] = va.z; As[c4 * 4 + 3][r] = va.w;
            float4 vb = *(const float4*)(Yb + (size_t)r * DD + kt + c4 * 4);
            Bs[c4 * 4 + 0][r] = vb.x; Bs[c4 * 4 + 1][r] = vb.y;
            Bs[c4 * 4 + 2][r] = vb.z; Bs[c4 * 4 + 3][r] = vb.w;
        }
        __syncthreads();
        #pragma unroll
        for (int kk = 0; kk < 16; kk++) {
            float a[8], b[8];
            *(float4*)(a)     = *(const float4*)&As[kk][ty * 8];
            *(float4*)(a + 4) = *(const float4*)&As[kk][ty * 8 + 4];
            *(float4*)(b)     = *(const float4*)&Bs[kk][tx * 8];
            *(float4*)(b + 4) = *(const float4*)&Bs[kk][tx * 8 + 4];
            #pragma unroll
            for (int i = 0; i < 8; i++)
                #pragma unroll
                for (int j = 0; j < 8; j++)
                    acc[i][j] = fmaf(a[i], b[j], acc[i][j]);
        }
    }
    int i0 = by * 128 + ty * 8;
    int j0 = bx * 128 + tx * 8;
    float inv = d_invstep;
    float ys[8];
    #pragma unroll
    for (int jj = 0; jj < 8; jj++) ys[jj] = d_ysq[j0 + jj];
    #pragma unroll
    for (int ii = 0; ii < 8; ii++) {
        float xs = d_xsq[i0 + ii];
        unsigned q[8];
        #pragma unroll
        for (int jj = 0; jj < 8; jj++) {
            float sq = xs + ys[jj] - 2.0f * acc[ii][jj];
            float c = sqrtf(fmaxf(sq, 1e-12f));
            unsigned qq = __float2uint_rn(c * inv);
            q[jj] = qq > 65535u ? 65535u : qq;
        }
        uint4 o;
        o.x = __byte_perm(q[0], q[1], 0x5410);
        o.y = __byte_perm(q[2], q[3], 0x5410);
        o.z = __byte_perm(q[4], q[5], 0x5410);
        o.w = __byte_perm(q[6], q[7], 0x5410);
        *(uint4*)(d_Cq + (size_t)(i0 + ii) * MM + j0) = o;
    }
}

// ---------------- g2 init (g=0) ----------------
__global__ void k_ginit() {
    d_g2[blockIdx.x * 256 + threadIdx.x] = d_fgC;
}

// ---------------- FUSED: f update (row LSE) + column partial accumulation ----------------
// 1024 threads, 8 columns/thread, FR=32 rows/block. One C read + one ex2 per element.
__global__ __launch_bounds__(1024, 1) void k_fused() {
    __shared__ float wm[32], ws[32];
    __shared__ float sF2;
    int t = threadIdx.x, lane = t & 31, w = t >> 5;
    float K2 = d_qK2, fgC = d_fgC;
    int row0 = blockIdx.x * FR;

    // this thread's 8 g2 values (columns t*8 .. t*8+7)
    float g2r[8];
    {
        float4 a = *(const float4*)(d_g2 + (size_t)t * 8);
        float4 b = *(const float4*)(d_g2 + (size_t)t * 8 + 4);
        g2r[0] = a.x; g2r[1] = a.y; g2r[2] = a.z; g2r[3] = a.w;
        g2r[4] = b.x; g2r[5] = b.y; g2r[6] = b.z; g2r[7] = b.w;
    }

    float acc[8];
    #pragma unroll
    for (int j = 0; j < 8; j++) acc[j] = 0.f;
    float St = -1e30f;

    const unsigned short* Cbase = d_Cq + (size_t)row0 * MM + (size_t)t * 8;

    for (int rr = 0; rr < FR; rr++) {
        uint4 cv = *(const uint4*)(Cbase + (size_t)rr * MM);
        float e[8];
        e[0] = fmaf(qf_lo(cv.x), -K2, g2r[0]);
        e[1] = fmaf(qf_hi(cv.x), -K2, g2r[1]);
        e[2] = fmaf(qf_lo(cv.y), -K2, g2r[2]);
        e[3] = fmaf(qf_hi(cv.y), -K2, g2r[3]);
        e[4] = fmaf(qf_lo(cv.z), -K2, g2r[4]);
        e[5] = fmaf(qf_hi(cv.z), -K2, g2r[5]);
        e[6] = fmaf(qf_lo(cv.w), -K2, g2r[6]);
        e[7] = fmaf(qf_hi(cv.w), -K2, g2r[7]);
        float mt = e[0];
        #pragma unroll
        for (int i = 1; i < 8; i++) mt = fmaxf(mt, e[i]);
        float s0 = 0.f, s1 = 0.f;
        #pragma unroll
        for (int i = 0; i < 8; i += 2) {
            e[i + 0] = ex2(e[i + 0] - mt); s0 += e[i + 0];
            e[i + 1] = ex2(e[i + 1] - mt); s1 += e[i + 1];
        }
        float sloc = s0 + s1;

        // warp fixed-shift reduce
        float M = mt;
        #pragma unroll
        for (int o = 16; o; o >>= 1) M = fmaxf(M, __shfl_xor_sync(0xffffffffu, M, o));
        float sw = sloc * ex2(mt - M);
        #pragma unroll
        for (int o = 16; o; o >>= 1) sw += __shfl_xor_sync(0xffffffffu, sw, o);
        if (lane == 0) { wm[w] = M; ws[w] = sw; }
        __syncthreads();
        if (w == 0) {
            float Mc = wm[lane], Sc = ws[lane];
            float Mf = Mc;
            #pragma unroll
            for (int o = 16; o; o >>= 1) Mf = fmaxf(Mf, __shfl_xor_sync(0xffffffffu, Mf, o));
            Sc *= ex2(Mc - Mf);
            #pragma unroll
            for (int o = 16; o; o >>= 1) Sc += __shfl_xor_sync(0xffffffffu, Sc, o);
            if (lane == 0) {
                float f = LOGA - LN2F * (Mf + lg2(Sc));
                d_f[row0 + rr] = f;
                sF2 = fmaf(f, LOG2EF, fgC);        // f2 (base-2 shifted)
            }
        }
        __syncthreads();

        // accumulate column partials: acc_j += e_j * 2^(mt + f2 - St)
        float arg = mt + sF2;
        if (arg > St) {
            float rs = ex2(St - arg);
            #pragma unroll
            for (int j = 0; j < 8; j++) acc[j] *= rs;
            St = arg;
            #pragma unroll
            for (int j = 0; j < 8; j++) acc[j] += e[j];
        } else {
            float coeff = ex2(arg - St);
            #pragma unroll
            for (int j = 0; j < 8; j++) acc[j] = fmaf(e[j], coeff, acc[j]);
        }
    }

    // write partials: column LSE partial = (m = St - g2_j, s = acc_j)
    size_t base = (size_t)blockIdx.x * MM + (size_t)t * 8;
    float4 pa, pb;
    pa.x = St - g2r[0]; pa.y = St - g2r[1]; pa.z = St - g2r[2]; pa.w = St - g2r[3];
    pb.x = St - g2r[4]; pb.y = St - g2r[5]; pb.z = St - g2r[6]; pb.w = St - g2r[7];
    *(float4*)(d_pm + base)     = pa;
    *(float4*)(d_pm + base + 4) = pb;
    float4 sa, sb;
    sa.x = acc[0]; sa.y = acc[1]; sa.z = acc[2]; sa.w = acc[3];
    sb.x = acc[4]; sb.y = acc[5]; sb.z = acc[6]; sb.w = acc[7];
    *(float4*)(d_ps + base)     = sa;
    *(float4*)(d_ps + base + 4) = sb;
}

// ---------------- g combine: two-pass max then sum over NCHUNK partials ----------------
__global__ __launch_bounds__(256) void k_gcomb() {
    int j = blockIdx.x * 256 + threadIdx.x;
    float M = -1e30f;
    #pragma unroll 8
    for (int c = 0; c < NCHUNK; c++)
        M = fmaxf(M, __ldg(&d_pm[(size_t)c * MM + j]));
    float S = 0.f;
    #pragma unroll 8
    for (int c = 0; c < NCHUNK; c++)
        S += __ldg(&d_ps[(size_t)c * MM + j]) * ex2(__ldg(&d_pm[(size_t)c * MM + j]) - M);
    float g = d_logb[j] - LN2F * (M + lg2(S));
    d_g[j] = g;
    d_g2[j] = fmaf(g, LOG2EF, d_fgC);
}

// ---------------- final OT loss ----------------
__global__ __launch_bounds__(256) void k_ot() {
    int t = threadIdx.x;
    int j = blockIdx.x * 1024 + t * 4;
    int r0 = blockIdx.y * (NN / CHUNKS);
    float K2 = d_qK2, stepf = d_step, qB = d_qdqB, fgC = d_fgC;
    float4 gv = *(const float4*)(d_g + j);
    float base[4];
    base[0] = fmaf(gv.x, LOG2EF, fgC);
    base[1] = fmaf(gv.y, LOG2EF, fgC);
    base[2] = fmaf(gv.z, LOG2EF, fgC);
    base[3] = fmaf(gv.w, LOG2EF, fgC);
    const unsigned short* Cb = d_Cq + j;
    float acc = 0.f;
    for (int r = r0; r < r0 + (NN / CHUNKS); r++) {
        float frl2 = __ldg(&d_f[r]) * LOG2EF;
        uint2 v = *(const uint2*)(Cb + (size_t)r * MM);
        float qf[4] = {qf_lo(v.x), qf_hi(v.x), qf_lo(v.y), qf_hi(v.y)};
        #pragma unroll
        for (int c = 0; c < 4; c++) {
            float p = ex2(fmaf(qf[c], -K2, base[c] + frl2));
            float cd = fmaf(qf[c], stepf, qB);
            acc = fmaf(p, cd, acc);
        }
    }
    double da = (double)acc;
    #pragma unroll
    for (int o = 16; o; o >>= 1) da += __shfl_down_sync(0xffffffffu, da, o);
    __shared__ double sd[8];
    int lane = t & 31, w = t >> 5;
    if (lane == 0) sd[w] = da;
    __syncthreads();
    if (t == 0) {
        double tot = 0.0;
        #pragma unroll
        for (int k = 0; k < 8; k++) tot += sd[k];
        atomicAdd(&d_ot, tot);
    }
}

// ---------------- supervised alignment MSE ----------------
__global__ __launch_bounds__(128) void k_dist(const float* __restrict__ X,
                                              const float* __restrict__ W,
                                              const int* __restrict__ al) {
    int row = blockIdx.x, t = threadIdx.x;
    long long idx; int mask;
    if (d_is64) {
        long long v = ((const long long*)al)[row];
        mask = (v != -1LL);
        idx = v < 0 ? 0 : v;
    } else {
        int v = al[row];
        mask = (v != -1);
        idx = v < 0 ? 0 : (long long)v;
    }
    float4 a = ((const float4*)X)[(size_t)row * (DD / 4) + t];
    float4 b = ((const float4*)W)[(size_t)idx * (DD / 4) + t];
    float dx = a.x - b.x, dy = a.y - b.y, dz = a.z - b.z, dw = a.w - b.w;
    float s = dx * dx + dy * dy + dz * dz + dw * dw;
    #pragma unroll
    for (int o = 16; o; o >>= 1) s += __shfl_down_sync(0xffffffffu, s, o);
    __shared__ float red[4];
    if ((t & 31) == 0) red[t >> 5] = s;
    __syncthreads();
    if (t == 0) {
        float tot = red[0] + red[1] + red[2] + red[3];
        if (mask) {
            atomicAdd(&d_sq, (double)tot);
            atomicAdd(&d_cnt, 1.0);
        }
    }
}

// ---------------- finalize ----------------
__global__ void k_final(float* out) {
    double dl = (d_cnt > 0.0) ? d_sq / (d_cnt * (double)DD) : 0.0;
    out[0] = (float)(d_ot + dl);
}

// ---------------- launch ----------------
extern "C" void kernel_launch(void* const* d_in, const int* in_sizes, int n_in,
                              void* d_out, int out_size) {
    const float* X  = (const float*)d_in[0];
    const float* W  = (const float*)d_in[1];
    const int*   AL = (const int*)d_in[2];
    const float* T  = (const float*)d_in[3];
    float* out = (float*)d_out;

    k_init<<<1, 1024>>>(T, AL);
    k_sqnorm<<<NN, 128>>>(X, 0);
    k_sqnorm<<<MM, 128>>>(W, 1);
    k_scale<<<1, 1024>>>();
    dim3 gg(MM / 128, NN / 128);
    k_gemm<<<gg, 256>>>(X, W);
    k_ginit<<<MM / 256, 256>>>();

    for (int it = 0; it < N_ITERS; it++) {
        k_fused<<<NN / FR, 1024>>>();
        k_gcomb<<<MM / 256, 256>>>();
    }

    k_ot<<<dim3(8, CHUNKS), 256>>>();
    k_dist<<<NN, 128>>>(X, W, AL);
    k_final<<<1, 1>>>(out);
}

// round 7
// speedup vs baseline: 1.6521x; 1.5367x over previous
#include <cuda_runtime.h>
#include <math.h>

#define NN 4096
#define MM 8192
#define DD 512
#define N_ITERS 200
#define LOGA   (-8.317766166719343f)   // log(1/4096)
#define CHUNKS 64
#define FROWS 8
#define LN2F    0.69314718055994531f
#define LOG2EF  1.44269504088896340f

// ---------------- device scratch ----------------
__device__ __align__(16) unsigned short d_Cq[(size_t)NN * MM];  // u16 quantized cost (64MB)
__device__ __align__(16) float d_f[NN];      // f' = f/reg (natural)
__device__ __align__(16) float d_fS[NN];     // f'*log2e + fgC   (for gpart dequant fold)
__device__ __align__(16) float d_fSu[NN];    // f'*log2e         (for frow fold)
__device__ __align__(16) float d_g[MM];      // g' = g/reg (natural)
__device__ __align__(16) float d_g2[MM];     // g'*log2e + fgC   (for frow dequant fold)
__device__ __align__(16) float d_g2u[MM];    // g'*log2e         (for gpart fold)
__device__ __align__(16) float d_logb[MM];
__device__ __align__(16) float d_xsq[NN];
__device__ __align__(16) float d_ysq[MM];
__device__ __align__(16) float d_ps[(size_t)CHUNKS * MM];   // 2 MB column partial sums
__device__ double d_ot;
__device__ double d_sq;
__device__ double d_cnt;
__device__ int    d_is64;
__device__ float d_qK2, d_fgC, d_step, d_invstep, d_qdqB;

__device__ __forceinline__ float ex2(float x) {
    float r; asm("ex2.approx.ftz.f32 %0, %1;" : "=f"(r) : "f"(x)); return r;
}
__device__ __forceinline__ float lg2(float x) {
    float r; asm("lg2.approx.ftz.f32 %0, %1;" : "=f"(r) : "f"(x)); return r;
}
__device__ __forceinline__ void lse2_merge(float mo, float so, float& m, float& s) {
    float mn = fmaxf(m, mo);
    s = s * ex2(m - mn) + so * ex2(mo - mn);
    m = mn;
}
// u16 -> float(2^23 + q), one PRMT
__device__ __forceinline__ float qf_lo(unsigned w) {
    return __uint_as_float(__byte_perm(w, 0x4B000000u, 0x7410));
}
__device__ __forceinline__ float qf_hi(unsigned w) {
    return __uint_as_float(__byte_perm(w, 0x4B000000u, 0x7432));
}

// ---------------- init ----------------
__global__ void k_init(const float* __restrict__ tgt, const int* __restrict__ al_raw) {
    __shared__ float red[32];
    __shared__ float s_total;
    int t = threadIdx.x;
    float s = 0.f;
    for (int j = t; j < MM; j += 1024) s += tgt[j];
    #pragma unroll
    for (int o = 16; o; o >>= 1) s += __shfl_down_sync(0xffffffffu, s, o);
    if ((t & 31) == 0) red[t >> 5] = s;
    __syncthreads();
    if (t < 32) {
        float v = red[t];
        #pragma unroll
        for (int o = 16; o; o >>= 1) v += __shfl_down_sync(0xffffffffu, v, o);
        if (t == 0) s_total = v;
    }
    __syncthreads();
    float lt = logf(s_total);
    for (int j = t; j < MM; j += 1024) {
        d_logb[j] = logf(tgt[j]) - lt;
        d_g[j] = 0.f;
    }
    int odd_nz = 0;
    for (int i = t; i < NN / 2; i += 1024)
        if (al_raw[2 * i + 1] != 0) odd_nz = 1;
    odd_nz = __syncthreads_or(odd_nz);
    if (t == 0) {
        d_is64 = odd_nz ? 0 : 1;
        d_ot = 0.0; d_sq = 0.0; d_cnt = 0.0;
    }
}

// ---------------- row squared norms ----------------
__global__ __launch_bounds__(128) void k_sqnorm(const float* __restrict__ X, int which) {
    int row = blockIdx.x, t = threadIdx.x;
    float4 v = ((const float4*)X)[(size_t)row * (DD / 4) + t];
    float s = v.x * v.x + v.y * v.y + v.z * v.z + v.w * v.w;
    #pragma unroll
    for (int o = 16; o; o >>= 1) s += __shfl_down_sync(0xffffffffu, s, o);
    __shared__ float red[4];
    if ((t & 31) == 0) red[t >> 5] = s;
    __syncthreads();
    if (t == 0) {
        float tot = red[0] + red[1] + red[2] + red[3];
        if (which == 0) d_xsq[row] = tot; else d_ysq[row] = tot;
    }
}

// ---------------- quantizer constants from norm bounds (C in [0, B]) ----------------
__global__ void k_scale() {
    __shared__ float red[32];
    int t = threadIdx.x;
    float mx = 0.f;
    for (int i = t; i < NN; i += 1024) mx = fmaxf(mx, d_xsq[i]);
    #pragma unroll
    for (int o = 16; o; o >>= 1) mx = fmaxf(mx, __shfl_xor_sync(0xffffffffu, mx, o));
    if ((t & 31) == 0) red[t >> 5] = mx;
    __syncthreads();
    float my = 0.f;
    for (int i = t; i < MM; i += 1024) my = fmaxf(my, d_ysq[i]);
    #pragma unroll
    for (int o = 16; o; o >>= 1) my = fmaxf(my, __shfl_xor_sync(0xffffffffu, my, o));
    __shared__ float red2[32];
    if ((t & 31) == 0) red2[t >> 5] = my;
    __syncthreads();
    if (t == 0) {
        float MX = 0.f, MY = 0.f;
        #pragma unroll
        for (int k = 0; k < 32; k++) { MX = fmaxf(MX, red[k]); MY = fmaxf(MY, red2[k]); }
        double B = 1.02 * ((double)sqrtf(MX) + (double)sqrtf(MY)) + 1e-3;
        double st = B / 65535.0;
        const double L2E = 1.4426950408889634;
        float K2f = (float)(10.0 * st * L2E);
        d_step = (float)st;
        d_invstep = (float)(1.0 / st);
        d_qK2 = K2f;
        d_fgC = (float)(8388608.0 * (double)K2f);   // 2^23*K2 fold for magic dequant
        d_qdqB = (float)(-8388608.0 * st);
    }
}

// ---------------- GEMM + cdist epilogue, writes u16 directly ----------------
__global__ __launch_bounds__(256) void k_gemm(const float* __restrict__ X, const float* __restrict__ Y) {
    __shared__ float As[16][128];
    __shared__ float Bs[16][128];
    int tid = threadIdx.x;
    int bx = blockIdx.x, by = blockIdx.y;
    int tx = tid & 15, ty = tid >> 4;
    float acc[8][8];
    #pragma unroll
    for (int i = 0; i < 8; i++)
        #pragma unroll
        for (int j = 0; j < 8; j++) acc[i][j] = 0.f;

    const float* Xb = X + (size_t)by * 128 * DD;
    const float* Yb = Y + (size_t)bx * 128 * DD;

    for (int kt = 0; kt < DD; kt += 16) {
        __syncthreads();
        #pragma unroll
        for (int i = 0; i < 2; i++) {
            int l  = tid + i * 256;
            int r  = l >> 2;
            int c4 = l & 3;
            float4 va = *(const float4*)(Xb + (size_t)r * DD + kt + c4 * 4);
            As[c4 * 4 + 0][r] = va.x; As[c4 * 4 + 1][r] = va.y;
            As[c4 * 4 + 2][r] = va.z; As[c4 * 4 + 3][r] = va.w;
            float4 vb = *(const float4*)(Yb + (size_t)r * DD + kt + c4 * 4);
            Bs[c4 * 4 + 0][r] = vb.x; Bs[c4 * 4 + 1][r] = vb.y;
            Bs[c4 * 4 + 2][r] = vb.z; Bs[c4 * 4 + 3][r] = vb.w;
        }
        __syncthreads();
        #pragma unroll
        for (int kk = 0; kk < 16; kk++) {
            float a[8], b[8];
            *(float4*)(a)     = *(const float4*)&As[kk][ty * 8];
            *(float4*)(a + 4) = *(const float4*)&As[kk][ty * 8 + 4];
            *(float4*)(b)     = *(const float4*)&Bs[kk][tx * 8];
            *(float4*)(b + 4) = *(const float4*)&Bs[kk][tx * 8 + 4];
            #pragma unroll
            for (int i = 0; i < 8; i++)
                #pragma unroll
                for (int j = 0; j < 8; j++)
                    acc[i][j] = fmaf(a[i], b[j], acc[i][j]);
        }
    }
    int i0 = by * 128 + ty * 8;
    int j0 = bx * 128 + tx * 8;
    float inv = d_invstep;
    float ys[8];
    #pragma unroll
    for (int jj = 0; jj < 8; jj++) ys[jj] = d_ysq[j0 + jj];
    #pragma unroll
    for (int ii = 0; ii < 8; ii++) {
        float xs = d_xsq[i0 + ii];
        unsigned q[8];
        #pragma unroll
        for (int jj = 0; jj < 8; jj++) {
            float sq = xs + ys[jj] - 2.0f * acc[ii][jj];
            float c = sqrtf(fmaxf(sq, 1e-12f));
            unsigned qq = __float2uint_rn(c * inv);
            q[jj] = qq > 65535u ? 65535u : qq;
        }
        uint4 o;
        o.x = __byte_perm(q[0], q[1], 0x5410);
        o.y = __byte_perm(q[2], q[3], 0x5410);
        o.z = __byte_perm(q[4], q[5], 0x5410);
        o.w = __byte_perm(q[6], q[7], 0x5410);
        *(uint4*)(d_Cq + (size_t)(i0 + ii) * MM + j0) = o;
    }
}

// ---------------- g staging init (g'=0) ----------------
__global__ void k_ginit() {
    int j = blockIdx.x * 256 + threadIdx.x;
    d_g2[j] = d_fgC;
    d_g2u[j] = 0.f;
}

// ---------------- iteration-0 f update: MAX-BASED row LSE (f'=0 would underflow) ----------------
__global__ __launch_bounds__(256) void k_frow0() {
    __shared__ float sg[MM];         // 32 KB staged d_g2
    __shared__ float red_m[8], red_s[8];
    int t = threadIdx.x, lane = t & 31, w = t >> 5;
    float K2 = d_qK2, fgC = d_fgC;
    #pragma unroll
    for (int k = 0; k < 8; k++)
        ((float4*)sg)[t + k * 256] = ((const float4*)d_g2)[t + k * 256];
    __syncthreads();

    int row0 = blockIdx.x * FROWS;
    for (int rr = 0; rr < FROWS; rr++) {
        int row = row0 + rr;
        const uint4* C4 = (const uint4*)(d_Cq + (size_t)row * MM);
        float x[32];
        #pragma unroll
        for (int k = 0; k < 4; k++) {
            uint4 cv = C4[t + k * 256];
            const float* sgp = sg + (t + k * 256) * 8;
            x[k * 8 + 0] = fmaf(qf_lo(cv.x), -K2, sgp[0]);
            x[k * 8 + 1] = fmaf(qf_hi(cv.x), -K2, sgp[1]);
            x[k * 8 + 2] = fmaf(qf_lo(cv.y), -K2, sgp[2]);
            x[k * 8 + 3] = fmaf(qf_hi(cv.y), -K2, sgp[3]);
            x[k * 8 + 4] = fmaf(qf_lo(cv.z), -K2, sgp[4]);
            x[k * 8 + 5] = fmaf(qf_hi(cv.z), -K2, sgp[5]);
            x[k * 8 + 6] = fmaf(qf_lo(cv.w), -K2, sgp[6]);
            x[k * 8 + 7] = fmaf(qf_hi(cv.w), -K2, sgp[7]);
        }
        float m = x[0];
        #pragma unroll
        for (int i = 1; i < 32; i++) m = fmaxf(m, x[i]);
        #pragma unroll
        for (int o = 16; o; o >>= 1) m = fmaxf(m, __shfl_xor_sync(0xffffffffu, m, o));
        float s0 = 0.f, s1 = 0.f, s2 = 0.f, s3 = 0.f;
        #pragma unroll
        for (int i = 0; i < 32; i += 4) {
            s0 += ex2(x[i + 0] - m);
            s1 += ex2(x[i + 1] - m);
            s2 += ex2(x[i + 2] - m);
            s3 += ex2(x[i + 3] - m);
        }
        float s = (s0 + s1) + (s2 + s3);
        #pragma unroll
        for (int o = 16; o; o >>= 1) s += __shfl_down_sync(0xffffffffu, s, o);
        if (lane == 0) { red_m[w] = m; red_s[w] = s; }
        __syncthreads();
        if (t == 0) {
            float fm = red_m[0], fs = red_s[0];
            #pragma unroll
            for (int k = 1; k < 8; k++) lse2_merge(red_m[k], red_s[k], fm, fs);
            float f = LOGA - LN2F * (fm + lg2(fs));
            float fle = f * LOG2EF;
            d_f[row] = f;
            d_fSu[row] = fle;
            d_fS[row] = fle + fgC;
        }
        __syncthreads();
    }
}

// ---------------- MAX-FREE f update: terms are bounded P entries (prev f folded) ----------------
__global__ __launch_bounds__(256) void k_frowm() {
    __shared__ float sg[MM];         // 32 KB staged d_g2
    __shared__ float red[FROWS][8];
    int t = threadIdx.x, lane = t & 31, w = t >> 5;
    float K2 = d_qK2, fgC = d_fgC;
    #pragma unroll
    for (int k = 0; k < 8; k++)
        ((float4*)sg)[t + k * 256] = ((const float4*)d_g2)[t + k * 256];
    __syncthreads();

    int row0 = blockIdx.x * FROWS;
    float rs[FROWS];
    #pragma unroll 1
    for (int rr = 0; rr < FROWS; rr++) {
        float f2p = __ldg(&d_fSu[row0 + rr]);
        const uint4* C4 = (const uint4*)(d_Cq + (size_t)(row0 + rr) * MM);
        float s0 = 0.f, s1 = 0.f, s2 = 0.f, s3 = 0.f;
        #pragma unroll
        for (int k = 0; k < 4; k++) {
            uint4 cv = C4[t + k * 256];
            const float* sgp = sg + (t + k * 256) * 8;
            s0 += ex2(fmaf(qf_lo(cv.x), -K2, sgp[0]) + f2p);
            s1 += ex2(fmaf(qf_hi(cv.x), -K2, sgp[1]) + f2p);
            s2 += ex2(fmaf(qf_lo(cv.y), -K2, sgp[2]) + f2p);
            s3 += ex2(fmaf(qf_hi(cv.y), -K2, sgp[3]) + f2p);
            s0 += ex2(fmaf(qf_lo(cv.z), -K2, sgp[4]) + f2p);
            s1 += ex2(fmaf(qf_hi(cv.z), -K2, sgp[5]) + f2p);
            s2 += ex2(fmaf(qf_lo(cv.w), -K2, sgp[6]) + f2p);
            s3 += ex2(fmaf(qf_hi(cv.w), -K2, sgp[7]) + f2p);
        }
        rs[rr] = (s0 + s1) + (s2 + s3);
    }
    // single reduction phase: warp-reduce each row, then warp w finalizes row w
    #pragma unroll
    for (int rr = 0; rr < FROWS; rr++) {
        float s = rs[rr];
        #pragma unroll
        for (int o = 16; o; o >>= 1) s += __shfl_xor_sync(0xffffffffu, s, o);
        if (lane == 0) red[rr][w] = s;
    }
    __syncthreads();
    {
        float v = (lane < 8) ? red[w][lane] : 0.f;
        #pragma unroll
        for (int o = 4; o; o >>= 1) v += __shfl_xor_sync(0xffffffffu, v, o);
        if (lane == 0) {
            float S = fmaxf(v, 1e-37f);
            float f2p = __ldg(&d_fSu[row0 + w]);
            float f = LOGA - LN2F * (lg2(S) - f2p);
            float fle = f * LOG2EF;
            d_f[row0 + w] = f;
            d_fSu[row0 + w] = fle;
            d_fS[row0 + w] = fle + fgC;
        }
    }
}

// ---------------- MAX-FREE g partials: column sums of P (old g folded) ----------------
__global__ __launch_bounds__(256) void k_gpartm() {
    int t = threadIdx.x;
    int j = blockIdx.x * 1024 + t * 4;
    int r0 = blockIdx.y * (NN / CHUNKS);     // 64 rows per chunk
    float K2 = d_qK2;
    float4 gu = *(const float4*)(d_g2u + j);
    float s0 = 0.f, s1 = 0.f, s2 = 0.f, s3 = 0.f;

    const unsigned short* Cb = d_Cq + j;
    #pragma unroll 4
    for (int r = r0; r < r0 + (NN / CHUNKS); r++) {
        float FA = __ldg(&d_fS[r]);
        uint2 v = *(const uint2*)(Cb + (size_t)r * MM);
        s0 += ex2(fmaf(qf_lo(v.x), -K2, FA) + gu.x);
        s1 += ex2(fmaf(qf_hi(v.x), -K2, FA) + gu.y);
        s2 += ex2(fmaf(qf_lo(v.y), -K2, FA) + gu.z);
        s3 += ex2(fmaf(qf_hi(v.y), -K2, FA) + gu.w);
    }
    *(float4*)(d_ps + (size_t)blockIdx.y * MM + j) = make_float4(s0, s1, s2, s3);
}

// ---------------- g combine: plain sum over chunks ----------------
__global__ __launch_bounds__(256) void k_gcomb() {
    int j = blockIdx.x * 256 + threadIdx.x;
    float V = 0.f;
    #pragma unroll 8
    for (int c = 0; c < CHUNKS; c++)
        V += __ldg(&d_ps[(size_t)c * MM + j]);
    V = fmaxf(V, 1e-37f);
    float g = d_logb[j] - LN2F * (lg2(V) - d_g2u[j]);
    float gle = g * LOG2EF;
    d_g[j] = g;
    d_g2[j] = gle + d_fgC;
    d_g2u[j] = gle;
}

// ---------------- final OT loss ----------------
__global__ __launch_bounds__(256) void k_ot() {
    int t = threadIdx.x;
    int j = blockIdx.x * 1024 + t * 4;
    int r0 = blockIdx.y * (NN / CHUNKS);
    float K2 = d_qK2, stepf = d_step, qB = d_qdqB, fgC = d_fgC;
    float4 gv = *(const float4*)(d_g + j);
    float base[4];
    base[0] = fmaf(gv.x, LOG2EF, fgC);
    base[1] = fmaf(gv.y, LOG2EF, fgC);
    base[2] = fmaf(gv.z, LOG2EF, fgC);
    base[3] = fmaf(gv.w, LOG2EF, fgC);
    const unsigned short* Cb = d_Cq + j;
    float acc = 0.f;
    for (int r = r0; r < r0 + (NN / CHUNKS); r++) {
        float frl2 = __ldg(&d_f[r]) * LOG2EF;
        uint2 v = *(const uint2*)(Cb + (size_t)r * MM);
        float qf[4] = {qf_lo(v.x), qf_hi(v.x), qf_lo(v.y), qf_hi(v.y)};
        #pragma unroll
        for (int c = 0; c < 4; c++) {
            float p = ex2(fmaf(qf[c], -K2, base[c] + frl2));
            float cd = fmaf(qf[c], stepf, qB);
            acc = fmaf(p, cd, acc);
        }
    }
    double da = (double)acc;
    #pragma unroll
    for (int o = 16; o; o >>= 1) da += __shfl_down_sync(0xffffffffu, da, o);
    __shared__ double sd[8];
    int lane = t & 31, w = t >> 5;
    if (lane == 0) sd[w] = da;
    __syncthreads();
    if (t == 0) {
        double tot = 0.0;
        #pragma unroll
        for (int k = 0; k < 8; k++) tot += sd[k];
        atomicAdd(&d_ot, tot);
    }
}

// ---------------- supervised alignment MSE ----------------
__global__ __launch_bounds__(128) void k_dist(const float* __restrict__ X,
                                              const float* __restrict__ W,
                                              const int* __restrict__ al) {
    int row = blockIdx.x, t = threadIdx.x;
    long long idx; int mask;
    if (d_is64) {
        long long v = ((const long long*)al)[row];
        mask = (v != -1LL);
        idx = v < 0 ? 0 : v;
    } else {
        int v = al[row];
        mask = (v != -1);
        idx = v < 0 ? 0 : (long long)v;
    }
    float4 a = ((const float4*)X)[(size_t)row * (DD / 4) + t];
    float4 b = ((const float4*)W)[(size_t)idx * (DD / 4) + t];
    float dx = a.x - b.x, dy = a.y - b.y, dz = a.z - b.z, dw = a.w - b.w;
    float s = dx * dx + dy * dy + dz * dz + dw * dw;
    #pragma unroll
    for (int o = 16; o; o >>= 1) s += __shfl_down_sync(0xffffffffu, s, o);
    __shared__ float red[4];
    if ((t & 31) == 0) red[t >> 5] = s;
    __syncthreads();
    if (t == 0) {
        float tot = red[0] + red[1] + red[2] + red[3];
        if (mask) {
            atomicAdd(&d_sq, (double)tot);
            atomicAdd(&d_cnt, 1.0);
        }
    }
}

// ---------------- finalize ----------------
__global__ void k_final(float* out) {
    double dl = (d_cnt > 0.0) ? d_sq / (d_cnt * (double)DD) : 0.0;
    out[0] = (float)(d_ot + dl);
}

// ---------------- launch ----------------
extern "C" void kernel_launch(void* const* d_in, const int* in_sizes, int n_in,
                              void* d_out, int out_size) {
    const float* X  = (const float*)d_in[0];
    const float* W  = (const float*)d_in[1];
    const int*   AL = (const int*)d_in[2];
    const float* T  = (const float*)d_in[3];
    float* out = (float*)d_out;

    k_init<<<1, 1024>>>(T, AL);
    k_sqnorm<<<NN, 128>>>(X, 0);
    k_sqnorm<<<MM, 128>>>(W, 1);
    k_scale<<<1, 1024>>>();
    dim3 gg(MM / 128, NN / 128);
    k_gemm<<<gg, 256>>>(X, W);
    k_ginit<<<MM / 256, 256>>>();

    for (int it = 0; it < N_ITERS; it++) {
        if (it == 0) k_frow0<<<NN / FROWS, 256>>>();
        else         k_frowm<<<NN / FROWS, 256>>>();
        k_gpartm<<<dim3(8, CHUNKS), 256>>>();
        k_gcomb<<<MM / 256, 256>>>();
    }

    k_ot<<<dim3(8, CHUNKS), 256>>>();
    k_dist<<<NN, 128>>>(X, W, AL);
    k_final<<<1, 1>>>(out);
}

// round 8
// speedup vs baseline: 2.1278x; 1.2879x over previous
#include <cuda_runtime.h>
#include <math.h>

#define NN 4096
#define MM 8192
#define DD 512
#define N_ITERS 200
#define LOGA   (-8.317766166719343f)   // log(1/4096)
#define GRID 128
#define RB (NN / GRID)                  // 32 rows per block
#define CHUNKS 64                       // for k_ot only
#define LN2F    0.69314718055994531f
#define LOG2EF  1.44269504088896340f

// ---------------- device scratch ----------------
__device__ __align__(16) unsigned short d_Cq[(size_t)NN * MM];  // u16 quantized cost (64MB)
__device__ __align__(16) float d_f[NN];      // final f' (natural), for k_ot
__device__ __align__(16) float d_g[MM];      // final g' (natural), for k_ot
__device__ __align__(16) float d_g2[MM];     // g'*log2e + fgC (staged fold)
__device__ __align__(16) float d_fSu[NN];    // initial f-fold seed (K2*qrmin)
__device__ __align__(16) float d_logb[MM];
__device__ __align__(16) float d_xsq[NN];
__device__ __align__(16) float d_ysq[MM];
__device__ __align__(16) unsigned d_qrmin[NN];
__device__ __align__(16) float d_ps[(size_t)GRID * MM];   // 4 MB column partial sums
__device__ double d_ot;
__device__ double d_sq;
__device__ double d_cnt;
__device__ int    d_is64;
__device__ float d_qK2, d_fgC, d_step, d_invstep, d_qdqB;
__device__ unsigned d_barcnt;

__device__ __forceinline__ float ex2(float x) {
    float r; asm("ex2.approx.ftz.f32 %0, %1;" : "=f"(r) : "f"(x)); return r;
}
__device__ __forceinline__ float lg2(float x) {
    float r; asm("lg2.approx.ftz.f32 %0, %1;" : "=f"(r) : "f"(x)); return r;
}
// u16 -> float(2^23 + q), one PRMT
__device__ __forceinline__ float qf_lo(unsigned w) {
    return __uint_as_float(__byte_perm(w, 0x4B000000u, 0x7410));
}
__device__ __forceinline__ float qf_hi(unsigned w) {
    return __uint_as_float(__byte_perm(w, 0x4B000000u, 0x7432));
}

// monotonic-counter grid barrier (counter reset by k_ginit before each replay)
__device__ __forceinline__ void gridbar(int tid, unsigned target) {
    __syncthreads();
    if (tid == 0) {
        __threadfence();
        atomicAdd(&d_barcnt, 1u);
        while (*(volatile unsigned*)&d_barcnt < target) { __nanosleep(64); }
    }
    __syncthreads();
}

// ---------------- init ----------------
__global__ void k_init(const float* __restrict__ tgt, const int* __restrict__ al_raw) {
    __shared__ float red[32];
    __shared__ float s_total;
    int t = threadIdx.x;
    float s = 0.f;
    for (int j = t; j < MM; j += 1024) s += tgt[j];
    #pragma unroll
    for (int o = 16; o; o >>= 1) s += __shfl_down_sync(0xffffffffu, s, o);
    if ((t & 31) == 0) red[t >> 5] = s;
    __syncthreads();
    if (t < 32) {
        float v = red[t];
        #pragma unroll
        for (int o = 16; o; o >>= 1) v += __shfl_down_sync(0xffffffffu, v, o);
        if (t == 0) s_total = v;
    }
    __syncthreads();
    float lt = logf(s_total);
    for (int j = t; j < MM; j += 1024) d_logb[j] = logf(tgt[j]) - lt;
    for (int i = t; i < NN; i += 1024) d_qrmin[i] = 0xFFFFu;
    int odd_nz = 0;
    for (int i = t; i < NN / 2; i += 1024)
        if (al_raw[2 * i + 1] != 0) odd_nz = 1;
    odd_nz = __syncthreads_or(odd_nz);
    if (t == 0) {
        d_is64 = odd_nz ? 0 : 1;
        d_ot = 0.0; d_sq = 0.0; d_cnt = 0.0;
    }
}

// ---------------- row squared norms ----------------
__global__ __launch_bounds__(128) void k_sqnorm(const float* __restrict__ X, int which) {
    int row = blockIdx.x, t = threadIdx.x;
    float4 v = ((const float4*)X)[(size_t)row * (DD / 4) + t];
    float s = v.x * v.x + v.y * v.y + v.z * v.z + v.w * v.w;
    #pragma unroll
    for (int o = 16; o; o >>= 1) s += __shfl_down_sync(0xffffffffu, s, o);
    __shared__ float red[4];
    if ((t & 31) == 0) red[t >> 5] = s;
    __syncthreads();
    if (t == 0) {
        float tot = red[0] + red[1] + red[2] + red[3];
        if (which == 0) d_xsq[row] = tot; else d_ysq[row] = tot;
    }
}

// ---------------- quantizer constants from norm bounds (C in [0, B]) ----------------
__global__ void k_scale() {
    __shared__ float red[32];
    int t = threadIdx.x;
    float mx = 0.f;
    for (int i = t; i < NN; i += 1024) mx = fmaxf(mx, d_xsq[i]);
    #pragma unroll
    for (int o = 16; o; o >>= 1) mx = fmaxf(mx, __shfl_xor_sync(0xffffffffu, mx, o));
    if ((t & 31) == 0) red[t >> 5] = mx;
    __syncthreads();
    float my = 0.f;
    for (int i = t; i < MM; i += 1024) my = fmaxf(my, d_ysq[i]);
    #pragma unroll
    for (int o = 16; o; o >>= 1) my = fmaxf(my, __shfl_xor_sync(0xffffffffu, my, o));
    __shared__ float red2[32];
    if ((t & 31) == 0) red2[t >> 5] = my;
    __syncthreads();
    if (t == 0) {
        float MX = 0.f, MY = 0.f;
        #pragma unroll
        for (int k = 0; k < 32; k++) { MX = fmaxf(MX, red[k]); MY = fmaxf(MY, red2[k]); }
        double B = 1.02 * ((double)sqrtf(MX) + (double)sqrtf(MY)) + 1e-3;
        double st = B / 65535.0;
        const double L2E = 1.4426950408889634;
        float K2f = (float)(10.0 * st * L2E);
        d_step = (float)st;
        d_invstep = (float)(1.0 / st);
        d_qK2 = K2f;
        d_fgC = (float)(8388608.0 * (double)K2f);   // 2^23*K2 fold for magic dequant
        d_qdqB = (float)(-8388608.0 * st);
    }
}

// ---------------- GEMM + cdist epilogue + per-row min, writes u16 ----------------
__global__ __launch_bounds__(256) void k_gemm(const float* __restrict__ X, const float* __restrict__ Y) {
    __shared__ float As[16][128];
    __shared__ float Bs[16][128];
    __shared__ unsigned rmin[128];
    int tid = threadIdx.x;
    int bx = blockIdx.x, by = blockIdx.y;
    int tx = tid & 15, ty = tid >> 4;
    if (tid < 128) rmin[tid] = 0xFFFFu;
    float acc[8][8];
    #pragma unroll
    for (int i = 0; i < 8; i++)
        #pragma unroll
        for (int j = 0; j < 8; j++) acc[i][j] = 0.f;

    const float* Xb = X + (size_t)by * 128 * DD;
    const float* Yb = Y + (size_t)bx * 128 * DD;

    for (int kt = 0; kt < DD; kt += 16) {
        __syncthreads();
        #pragma unroll
        for (int i = 0; i < 2; i++) {
            int l  = tid + i * 256;
            int r  = l >> 2;
            int c4 = l & 3;
            float4 va = *(const float4*)(Xb + (size_t)r * DD + kt + c4 * 4);
            As[c4 * 4 + 0][r] = va.x; As[c4 * 4 + 1][r] = va.y;
            As[c4 * 4 + 2][r] = va.z; As[c4 * 4 + 3][r] = va.w;
            float4 vb = *(const float4*)(Yb + (size_t)r * DD + kt + c4 * 4);
            Bs[c4 * 4 + 0][r] = vb.x; Bs[c4 * 4 + 1][r] = vb.y;
            Bs[c4 * 4 + 2][r] = vb.z; Bs[c4 * 4 + 3][r] = vb.w;
        }
        __syncthreads();
        #pragma unroll
        for (int kk = 0; kk < 16; kk++) {
            float a[8], b[8];
            *(float4*)(a)     = *(const float4*)&As[kk][ty * 8];
            *(float4*)(a + 4) = *(const float4*)&As[kk][ty * 8 + 4];
            *(float4*)(b)     = *(const float4*)&Bs[kk][tx * 8];
            *(float4*)(b + 4) = *(const float4*)&Bs[kk][tx * 8 + 4];
            #pragma unroll
            for (int i = 0; i < 8; i++)
                #pragma unroll
                for (int j = 0; j < 8; j++)
                    acc[i][j] = fmaf(a[i], b[j], acc[i][j]);
        }
    }
    int i0 = by * 128 + ty * 8;
    int j0 = bx * 128 + tx * 8;
    float inv = d_invstep;
    float ys[8];
    #pragma unroll
    for (int jj = 0; jj < 8; jj++) ys[jj] = d_ysq[j0 + jj];
    #pragma unroll
    for (int ii = 0; ii < 8; ii++) {
        float xs = d_xsq[i0 + ii];
        unsigned q[8];
        unsigned qm = 0xFFFFu;
        #pragma unroll
        for (int jj = 0; jj < 8; jj++) {
            float sq = xs + ys[jj] - 2.0f * acc[ii][jj];
            float c = sqrtf(fmaxf(sq, 1e-12f));
            unsigned qq = __float2uint_rn(c * inv);
            q[jj] = qq > 65535u ? 65535u : qq;
            qm = min(qm, q[jj]);
        }
        atomicMin(&rmin[ty * 8 + ii], qm);
        uint4 o;
        o.x = __byte_perm(q[0], q[1], 0x5410);
        o.y = __byte_perm(q[2], q[3], 0x5410);
        o.z = __byte_perm(q[4], q[5], 0x5410);
        o.w = __byte_perm(q[6], q[7], 0x5410);
        *(uint4*)(d_Cq + (size_t)(i0 + ii) * MM + j0) = o;
    }
    __syncthreads();
    if (tid < 128) atomicMin(&d_qrmin[by * 128 + tid], rmin[tid]);
}

// ---------------- staging init: g2=fgC, fSu seed, barrier reset ----------------
__global__ void k_ginit() {
    int j = blockIdx.x * 256 + threadIdx.x;
    d_g2[j] = d_fgC;
    if (j < NN) d_fSu[j] = d_qK2 * (float)d_qrmin[j];
    if (j == 0) d_barcnt = 0u;
}

// ---------------- PERSISTENT LOOP: all 200 Sinkhorn iterations ----------------
__global__ __launch_bounds__(1024, 1) void k_loop() {
    __shared__ float sg[MM];       // staged g2 (32 KB)
    __shared__ float sf[RB];       // this block's f-fold (fle + fgC)
    int t = threadIdx.x;
    int blk = blockIdx.x;
    int w = t >> 5, l = t & 31;
    float K2 = d_qK2, fgC = d_fgC;
    int row = blk * RB + w;
    const uint4* Crow = (const uint4*)(d_Cq + (size_t)row * MM);
    const uint4* Cblk = (const uint4*)(d_Cq + (size_t)blk * RB * MM) + t;
    float f2p = d_fSu[row];        // per-warp fold (uniform across lanes)
    unsigned bcnt = 0;

    for (int it = 0; it < N_ITERS; it++) {
        // stage g2
        ((float4*)sg)[t]        = ((const float4*)d_g2)[t];
        ((float4*)sg)[t + 1024] = ((const float4*)d_g2)[t + 1024];
        __syncthreads();

        // ---- f-pass: warp w owns row ----
        float s0 = 0.f, s1 = 0.f, s2 = 0.f, s3 = 0.f;
        #pragma unroll 4
        for (int k = 0; k < 32; k++) {
            uint4 cv = Crow[k * 32 + l];
            const float* sp = sg + ((k * 32 + l) << 3);
            s0 += ex2(fmaf(qf_lo(cv.x), -K2, sp[0]) + f2p);
            s1 += ex2(fmaf(qf_hi(cv.x), -K2, sp[1]) + f2p);
            s2 += ex2(fmaf(qf_lo(cv.y), -K2, sp[2]) + f2p);
            s3 += ex2(fmaf(qf_hi(cv.y), -K2, sp[3]) + f2p);
            s0 += ex2(fmaf(qf_lo(cv.z), -K2, sp[4]) + f2p);
            s1 += ex2(fmaf(qf_hi(cv.z), -K2, sp[5]) + f2p);
            s2 += ex2(fmaf(qf_lo(cv.w), -K2, sp[6]) + f2p);
            s3 += ex2(fmaf(qf_hi(cv.w), -K2, sp[7]) + f2p);
        }
        float S = (s0 + s1) + (s2 + s3);
        #pragma unroll
        for (int o = 16; o; o >>= 1) S += __shfl_xor_sync(0xffffffffu, S, o);
        S = fmaxf(S, 1e-37f);
        float f = LOGA - LN2F * (lg2(S) - f2p);
        float fle = f * LOG2EF;
        f2p = fle;
        if (l == 0) {
            sf[w] = fle + fgC;
            if (it == N_ITERS - 1) d_f[row] = f;
        }
        __syncthreads();

        // ---- gpart: thread t owns cols t*8..t*8+7 over this block's 32 rows ----
        float a0 = 0.f, a1 = 0.f, a2 = 0.f, a3 = 0.f;
        float a4 = 0.f, a5 = 0.f, a6 = 0.f, a7 = 0.f;
        #pragma unroll 4
        for (int rr = 0; rr < RB; rr++) {
            float FA = sf[rr];
            uint4 cv = Cblk[(size_t)rr * 1024];
            a0 += ex2(fmaf(qf_lo(cv.x), -K2, FA));
            a1 += ex2(fmaf(qf_hi(cv.x), -K2, FA));
            a2 += ex2(fmaf(qf_lo(cv.y), -K2, FA));
            a3 += ex2(fmaf(qf_hi(cv.y), -K2, FA));
            a4 += ex2(fmaf(qf_lo(cv.z), -K2, FA));
            a5 += ex2(fmaf(qf_hi(cv.z), -K2, FA));
            a6 += ex2(fmaf(qf_lo(cv.w), -K2, FA));
            a7 += ex2(fmaf(qf_hi(cv.w), -K2, FA));
        }
        {
            float* dst = d_ps + (size_t)blk * MM + (size_t)t * 8;
            *(float4*)(dst)     = make_float4(a0, a1, a2, a3);
            *(float4*)(dst + 4) = make_float4(a4, a5, a6, a7);
        }
        bcnt += GRID;
        gridbar(t, bcnt);

        // ---- gcomb: block owns 64 columns ----
        {
            int col = blk * 64 + (t >> 4);
            int sub = t & 15;
            float V = 0.f;
            #pragma unroll
            for (int c8 = 0; c8 < 8; c8++)
                V += d_ps[(size_t)(sub * 8 + c8) * MM + col];
            #pragma unroll
            for (int o = 8; o; o >>= 1) V += __shfl_xor_sync(0xffffffffu, V, o, 16);
            if (sub == 0) {
                V = fmaxf(V, 1e-37f);
                float g = d_logb[col] - LN2F * lg2(V);
                d_g2[col] = fmaf(g, LOG2EF, fgC);
                if (it == N_ITERS - 1) d_g[col] = g;
            }
        }
        bcnt += GRID;
        gridbar(t, bcnt);
    }
}

// ---------------- final OT loss ----------------
__global__ __launch_bounds__(256) void k_ot() {
    int t = threadIdx.x;
    int j = blockIdx.x * 1024 + t * 4;
    int r0 = blockIdx.y * (NN / CHUNKS);
    float K2 = d_qK2, stepf = d_step, qB = d_qdqB, fgC = d_fgC;
    float4 gv = *(const float4*)(d_g + j);
    float base[4];
    base[0] = fmaf(gv.x, LOG2EF, fgC);
    base[1] = fmaf(gv.y, LOG2EF, fgC);
    base[2] = fmaf(gv.z, LOG2EF, fgC);
    base[3] = fmaf(gv.w, LOG2EF, fgC);
    const unsigned short* Cb = d_Cq + j;
    float acc = 0.f;
    for (int r = r0; r < r0 + (NN / CHUNKS); r++) {
        float frl2 = __ldg(&d_f[r]) * LOG2EF;
        uint2 v = *(const uint2*)(Cb + (size_t)r * MM);
        float qf[4] = {qf_lo(v.x), qf_hi(v.x), qf_lo(v.y), qf_hi(v.y)};
        #pragma unroll
        for (int c = 0; c < 4; c++) {
            float p = ex2(fmaf(qf[c], -K2, base[c] + frl2));
            float cd = fmaf(qf[c], stepf, qB);
            acc = fmaf(p, cd, acc);
        }
    }
    double da = (double)acc;
    #pragma unroll
    for (int o = 16; o; o >>= 1) da += __shfl_down_sync(0xffffffffu, da, o);
    __shared__ double sd[8];
    int lane = t & 31, w = t >> 5;
    if (lane == 0) sd[w] = da;
    __syncthreads();
    if (t == 0) {
        double tot = 0.0;
        #pragma unroll
        for (int k = 0; k < 8; k++) tot += sd[k];
        atomicAdd(&d_ot, tot);
    }
}

// ---------------- supervised alignment MSE ----------------
__global__ __launch_bounds__(128) void k_dist(const float* __restrict__ X,
                                              const float* __restrict__ W,
                                              const int* __restrict__ al) {
    int row = blockIdx.x, t = threadIdx.x;
    long long idx; int mask;
    if (d_is64) {
        long long v = ((const long long*)al)[row];
        mask = (v != -1LL);
        idx = v < 0 ? 0 : v;
    } else {
        int v = al[row];
        mask = (v != -1);
        idx = v < 0 ? 0 : (long long)v;
    }
    float4 a = ((const float4*)X)[(size_t)row * (DD / 4) + t];
    float4 b = ((const float4*)W)[(size_t)idx * (DD / 4) + t];
    float dx = a.x - b.x, dy = a.y - b.y, dz = a.z - b.z, dw = a.w - b.w;
    float s = dx * dx + dy * dy + dz * dz + dw * dw;
    #pragma unroll
    for (int o = 16; o; o >>= 1) s += __shfl_down_sync(0xffffffffu, s, o);
    __shared__ float red[4];
    if ((t & 31) == 0) red[t >> 5] = s;
    __syncthreads();
    if (t == 0) {
        float tot = red[0] + red[1] + red[2] + red[3];
        if (mask) {
            atomicAdd(&d_sq, (double)tot);
            atomicAdd(&d_cnt, 1.0);
        }
    }
}

// ---------------- finalize ----------------
__global__ void k_final(float* out) {
    double dl = (d_cnt > 0.0) ? d_sq / (d_cnt * (double)DD) : 0.0;
    out[0] = (float)(d_ot + dl);
}

// ---------------- launch ----------------
extern "C" void kernel_launch(void* const* d_in, const int* in_sizes, int n_in,
                              void* d_out, int out_size) {
    const float* X  = (const float*)d_in[0];
    const float* W  = (const float*)d_in[1];
    const int*   AL = (const int*)d_in[2];
    const float* T  = (const float*)d_in[3];
    float* out = (float*)d_out;

    k_init<<<1, 1024>>>(T, AL);
    k_sqnorm<<<NN, 128>>>(X, 0);
    k_sqnorm<<<MM, 128>>>(W, 1);
    k_scale<<<1, 1024>>>();
    dim3 gg(MM / 128, NN / 128);
    k_gemm<<<gg, 256>>>(X, W);
    k_ginit<<<MM / 256, 256>>>();

    k_loop<<<GRID, 1024>>>();

    k_ot<<<dim3(8, CHUNKS), 256>>>();
    k_dist<<<NN, 128>>>(X, W, AL);
    k_final<<<1, 1>>>(out);
}

// round 10
// speedup vs baseline: 2.2262x; 1.0462x over previous
#include <cuda_runtime.h>
#include <math.h>

#define NN 4096
#define MM 8192
#define DD 512
#define N_ITERS 200
#define LOGA   (-8.317766166719343f)   // log(1/4096)
#define GRID 148
#define CHUNKS 64                       // for k_ot only
#define LN2F    0.69314718055994531f
#define LOG2EF  1.44269504088896340f

// ---------------- device scratch ----------------
__device__ __align__(16) unsigned short d_Cq[(size_t)NN * MM];  // u16 quantized cost (64MB)
__device__ __align__(16) float d_f[NN];      // final f' (natural), for k_ot
__device__ __align__(16) float d_g[MM];      // final g' (natural), for k_ot
__device__ __align__(16) float d_g2[MM];     // g'*log2e + fgC (staged fold)
__device__ __align__(16) float d_fSu[NN];    // initial f-fold seed (K2*qrmin)
__device__ __align__(16) float d_logb[MM];
__device__ __align__(16) float d_xsq[NN];
__device__ __align__(16) float d_ysq[MM];
__device__ __align__(16) unsigned d_qrmin[NN];
__device__ __align__(16) float d_ps[(size_t)GRID * MM];   // ~4.8 MB column partial sums
__device__ double d_ot;
__device__ double d_sq;
__device__ double d_cnt;
__device__ int    d_is64;
__device__ float d_qK2, d_fgC, d_step, d_invstep, d_qdqB;
__device__ unsigned d_barcnt;

__device__ __forceinline__ float ex2(float x) {
    float r; asm("ex2.approx.ftz.f32 %0, %1;" : "=f"(r) : "f"(x)); return r;
}
__device__ __forceinline__ float lg2(float x) {
    float r; asm("lg2.approx.ftz.f32 %0, %1;" : "=f"(r) : "f"(x)); return r;
}
// u16 -> float(2^23 + q), one PRMT
__device__ __forceinline__ float qf_lo(unsigned w) {
    return __uint_as_float(__byte_perm(w, 0x4B000000u, 0x7410));
}
__device__ __forceinline__ float qf_hi(unsigned w) {
    return __uint_as_float(__byte_perm(w, 0x4B000000u, 0x7432));
}

// monotonic-counter grid barrier (counter reset by k_ginit before each replay)
__device__ __forceinline__ void gridbar(int tid, unsigned target) {
    __syncthreads();
    if (tid == 0) {
        __threadfence();
        atomicAdd(&d_barcnt, 1u);
        while (*(volatile unsigned*)&d_barcnt < target) { __nanosleep(64); }
    }
    __syncthreads();
}

// ---------------- init ----------------
__global__ void k_init(const float* __restrict__ tgt, const int* __restrict__ al_raw) {
    __shared__ float red[32];
    __shared__ float s_total;
    int t = threadIdx.x;
    float s = 0.f;
    for (int j = t; j < MM; j += 1024) s += tgt[j];
    #pragma unroll
    for (int o = 16; o; o >>= 1) s += __shfl_down_sync(0xffffffffu, s, o);
    if ((t & 31) == 0) red[t >> 5] = s;
    __syncthreads();
    if (t < 32) {
        float v = red[t];
        #pragma unroll
        for (int o = 16; o; o >>= 1) v += __shfl_down_sync(0xffffffffu, v, o);
        if (t == 0) s_total = v;
    }
    __syncthreads();
    float lt = logf(s_total);
    for (int j = t; j < MM; j += 1024) d_logb[j] = logf(tgt[j]) - lt;
    for (int i = t; i < NN; i += 1024) d_qrmin[i] = 0xFFFFu;
    int odd_nz = 0;
    for (int i = t; i < NN / 2; i += 1024)
        if (al_raw[2 * i + 1] != 0) odd_nz = 1;
    odd_nz = __syncthreads_or(odd_nz);
    if (t == 0) {
        d_is64 = odd_nz ? 0 : 1;
        d_ot = 0.0; d_sq = 0.0; d_cnt = 0.0;
    }
}

// ---------------- row squared norms ----------------
__global__ __launch_bounds__(128) void k_sqnorm(const float* __restrict__ X, int which) {
    int row = blockIdx.x, t = threadIdx.x;
    float4 v = ((const float4*)X)[(size_t)row * (DD / 4) + t];
    float s = v.x * v.x + v.y * v.y + v.z * v.z + v.w * v.w;
    #pragma unroll
    for (int o = 16; o; o >>= 1) s += __shfl_down_sync(0xffffffffu, s, o);
    __shared__ float red[4];
    if ((t & 31) == 0) red[t >> 5] = s;
    __syncthreads();
    if (t == 0) {
        float tot = red[0] + red[1] + red[2] + red[3];
        if (which == 0) d_xsq[row] = tot; else d_ysq[row] = tot;
    }
}

// ---------------- quantizer constants from norm bounds (C in [0, B]) ----------------
__global__ void k_scale() {
    __shared__ float red[32];
    int t = threadIdx.x;
    float mx = 0.f;
    for (int i = t; i < NN; i += 1024) mx = fmaxf(mx, d_xsq[i]);
    #pragma unroll
    for (int o = 16; o; o >>= 1) mx = fmaxf(mx, __shfl_xor_sync(0xffffffffu, mx, o));
    if ((t & 31) == 0) red[t >> 5] = mx;
    __syncthreads();
    float my = 0.f;
    for (int i = t; i < MM; i += 1024) my = fmaxf(my, d_ysq[i]);
    #pragma unroll
    for (int o = 16; o; o >>= 1) my = fmaxf(my, __shfl_xor_sync(0xffffffffu, my, o));
    __shared__ float red2[32];
    if ((t & 31) == 0) red2[t >> 5] = my;
    __syncthreads();
    if (t == 0) {
        float MX = 0.f, MY = 0.f;
        #pragma unroll
        for (int k = 0; k < 32; k++) { MX = fmaxf(MX, red[k]); MY = fmaxf(MY, red2[k]); }
        double B = 1.02 * ((double)sqrtf(MX) + (double)sqrtf(MY)) + 1e-3;
        double st = B / 65535.0;
        const double L2E = 1.4426950408889634;
        float K2f = (float)(10.0 * st * L2E);
        d_step = (float)st;
        d_invstep = (float)(1.0 / st);
        d_qK2 = K2f;
        d_fgC = (float)(8388608.0 * (double)K2f);   // 2^23*K2 fold for magic dequant
        d_qdqB = (float)(-8388608.0 * st);
    }
}

// ---------------- GEMM (reg-prefetch double buffer) + cdist epilogue + row min ----------------
__global__ __launch_bounds__(256, 2) void k_gemm(const float* __restrict__ X, const float* __restrict__ Y) {
    __shared__ float As[16][128];
    __shared__ float Bs[16][128];
    __shared__ unsigned rmin[128];
    int tid = threadIdx.x;
    int bx = blockIdx.x, by = blockIdx.y;
    int tx = tid & 15, ty = tid >> 4;
    if (tid < 128) rmin[tid] = 0xFFFFu;
    float acc[8][8];
    #pragma unroll
    for (int i = 0; i < 8; i++)
        #pragma unroll
        for (int j = 0; j < 8; j++) acc[i][j] = 0.f;

    const float* Xb = X + (size_t)by * 128 * DD;
    const float* Yb = Y + (size_t)bx * 128 * DD;

    int l0 = tid, r0i = l0 >> 2, c40 = (l0 & 3) * 4;
    int l1 = tid + 256, r1i = l1 >> 2, c41 = (l1 & 3) * 4;

    float4 va[2], vb[2];
    va[0] = *(const float4*)(Xb + (size_t)r0i * DD + c40);
    va[1] = *(const float4*)(Xb + (size_t)r1i * DD + c41);
    vb[0] = *(const float4*)(Yb + (size_t)r0i * DD + c40);
    vb[1] = *(const float4*)(Yb + (size_t)r1i * DD + c41);

    for (int kt = 0; kt < DD; kt += 16) {
        __syncthreads();
        As[c40 + 0][r0i] = va[0].x; As[c40 + 1][r0i] = va[0].y;
        As[c40 + 2][r0i] = va[0].z; As[c40 + 3][r0i] = va[0].w;
        As[c41 + 0][r1i] = va[1].x; As[c41 + 1][r1i] = va[1].y;
        As[c41 + 2][r1i] = va[1].z; As[c41 + 3][r1i] = va[1].w;
        Bs[c40 + 0][r0i] = vb[0].x; Bs[c40 + 1][r0i] = vb[0].y;
        Bs[c40 + 2][r0i] = vb[0].z; Bs[c40 + 3][r0i] = vb[0].w;
        Bs[c41 + 0][r1i] = vb[1].x; Bs[c41 + 1][r1i] = vb[1].y;
        Bs[c41 + 2][r1i] = vb[1].z; Bs[c41 + 3][r1i] = vb[1].w;
        __syncthreads();
        if (kt + 16 < DD) {
            va[0] = *(const float4*)(Xb + (size_t)r0i * DD + kt + 16 + c40);
            va[1] = *(const float4*)(Xb + (size_t)r1i * DD + kt + 16 + c41);
            vb[0] = *(const float4*)(Yb + (size_t)r0i * DD + kt + 16 + c40);
            vb[1] = *(const float4*)(Yb + (size_t)r1i * DD + kt + 16 + c41);
        }
        #pragma unroll
        for (int kk = 0; kk < 16; kk++) {
            float a[8], b[8];
            *(float4*)(a)     = *(const float4*)&As[kk][ty * 8];
            *(float4*)(a + 4) = *(const float4*)&As[kk][ty * 8 + 4];
            *(float4*)(b)     = *(const float4*)&Bs[kk][tx * 8];
            *(float4*)(b + 4) = *(const float4*)&Bs[kk][tx * 8 + 4];
            #pragma unroll
            for (int i = 0; i < 8; i++)
                #pragma unroll
                for (int j = 0; j < 8; j++)
                    acc[i][j] = fmaf(a[i], b[j], acc[i][j]);
        }
    }
    int i0 = by * 128 + ty * 8;
    int j0 = bx * 128 + tx * 8;
    float inv = d_invstep;
    float ys[8];
    #pragma unroll
    for (int jj = 0; jj < 8; jj++) ys[jj] = d_ysq[j0 + jj];
    #pragma unroll
    for (int ii = 0; ii < 8; ii++) {
        float xs = d_xsq[i0 + ii];
        unsigned q[8];
        unsigned qm = 0xFFFFu;
        #pragma unroll
        for (int jj = 0; jj < 8; jj++) {
            float sq = xs + ys[jj] - 2.0f * acc[ii][jj];
            float c = sqrtf(fmaxf(sq, 1e-12f));
            unsigned qq = __float2uint_rn(c * inv);
            q[jj] = qq > 65535u ? 65535u : qq;
            qm = min(qm, q[jj]);
        }
        atomicMin(&rmin[ty * 8 + ii], qm);
        uint4 o;
        o.x = __byte_perm(q[0], q[1], 0x5410);
        o.y = __byte_perm(q[2], q[3], 0x5410);
        o.z = __byte_perm(q[4], q[5], 0x5410);
        o.w = __byte_perm(q[6], q[7], 0x5410);
        *(uint4*)(d_Cq + (size_t)(i0 + ii) * MM + j0) = o;
    }
    __syncthreads();
    if (tid < 128) atomicMin(&d_qrmin[by * 128 + tid], rmin[tid]);
}

// ---------------- staging init: g2=fgC, fSu seed, barrier reset ----------------
__global__ void k_ginit() {
    int j = blockIdx.x * 256 + threadIdx.x;
    d_g2[j] = d_fgC;
    if (j < NN) d_fSu[j] = d_qK2 * (float)d_qrmin[j];
    if (j == 0) d_barcnt = 0u;
}

// ---------------- PERSISTENT LOOP: all 200 Sinkhorn iterations, 148 blocks ----------------
__global__ __launch_bounds__(1024, 1) void k_loop() {
    __shared__ float sg[MM];       // staged g2 (32 KB)
    __shared__ float sf[32];       // this block's f-fold (fle + fgC)
    int t = threadIdx.x;
    int blk = blockIdx.x;
    int w = t >> 5, l = t & 31;
    float K2 = d_qK2, fgC = d_fgC;
    int r0 = (blk * NN) / GRID, r1 = ((blk + 1) * NN) / GRID;
    int nr = r1 - r0;                            // 27 or 28 rows
    int c0 = (blk * MM) / GRID, c1 = ((blk + 1) * MM) / GRID;
    int row = r0 + w;
    bool factive = (w < nr);                     // warp-uniform guard (safe w/ shfl)
    const uint4* Crow = (const uint4*)(d_Cq + (size_t)row * MM);
    const uint4* Cblk = (const uint4*)(d_Cq + (size_t)r0 * MM) + t;
    float f2p = factive ? d_fSu[row] : 0.f;
    // gcomb: 16 threads per column; colc CLAMPED so every lane of every warp
    // executes the shfl_sync (no partial-warp mask hang) and d_ps reads stay
    // in-bounds; the out-of-range tail only skips the final scalar write.
    int colc = min(c0 + (t >> 4), MM - 1);
    bool cwrite = (c0 + (t >> 4)) < c1;
    int sub = t & 15;
    unsigned bcnt = 0;

    for (int it = 0; it < N_ITERS; it++) {
        // stage g2 (L2-coherent loads: written by other blocks)
        ((float4*)sg)[t]        = __ldcg(((const float4*)d_g2) + t);
        ((float4*)sg)[t + 1024] = __ldcg(((const float4*)d_g2) + t + 1024);
        __syncthreads();

        // ---- f-pass: warp w owns row r0+w ----
        if (factive) {
            float s0 = 0.f, s1 = 0.f, s2 = 0.f, s3 = 0.f;
            #pragma unroll 4
            for (int k = 0; k < 32; k++) {
                uint4 cv = Crow[k * 32 + l];
                const float* sp = sg + ((k * 32 + l) << 3);
                s0 += ex2(fmaf(qf_lo(cv.x), -K2, sp[0]) + f2p);
                s1 += ex2(fmaf(qf_hi(cv.x), -K2, sp[1]) + f2p);
                s2 += ex2(fmaf(qf_lo(cv.y), -K2, sp[2]) + f2p);
                s3 += ex2(fmaf(qf_hi(cv.y), -K2, sp[3]) + f2p);
                s0 += ex2(fmaf(qf_lo(cv.z), -K2, sp[4]) + f2p);
                s1 += ex2(fmaf(qf_hi(cv.z), -K2, sp[5]) + f2p);
                s2 += ex2(fmaf(qf_lo(cv.w), -K2, sp[6]) + f2p);
                s3 += ex2(fmaf(qf_hi(cv.w), -K2, sp[7]) + f2p);
            }
            float S = (s0 + s1) + (s2 + s3);
            #pragma unroll
            for (int o = 16; o; o >>= 1) S += __shfl_xor_sync(0xffffffffu, S, o);
            S = fmaxf(S, 1e-37f);
            float f = LOGA - LN2F * (lg2(S) - f2p);
            float fle = f * LOG2EF;
            f2p = fle;
            if (l == 0) {
                sf[w] = fle + fgC;
                if (it == N_ITERS - 1) d_f[row] = f;
            }
        }
        __syncthreads();

        // ---- gpart: thread t owns cols t*8..t*8+7 over this block's rows ----
        float a0 = 0.f, a1 = 0.f, a2 = 0.f, a3 = 0.f;
        float a4 = 0.f, a5 = 0.f, a6 = 0.f, a7 = 0.f;
        #pragma unroll 4
        for (int rr = 0; rr < nr; rr++) {
            float FA = sf[rr];
            uint4 cv = Cblk[(size_t)rr * 1024];
            a0 += ex2(fmaf(qf_lo(cv.x), -K2, FA));
            a1 += ex2(fmaf(qf_hi(cv.x), -K2, FA));
            a2 += ex2(fmaf(qf_lo(cv.y), -K2, FA));
            a3 += ex2(fmaf(qf_hi(cv.y), -K2, FA));
            a4 += ex2(fmaf(qf_lo(cv.z), -K2, FA));
            a5 += ex2(fmaf(qf_hi(cv.z), -K2, FA));
            a6 += ex2(fmaf(qf_lo(cv.w), -K2, FA));
            a7 += ex2(fmaf(qf_hi(cv.w), -K2, FA));
        }
        {
            float* dst = d_ps + (size_t)blk * MM + (size_t)t * 8;
            *(float4*)(dst)     = make_float4(a0, a1, a2, a3);
            *(float4*)(dst + 4) = make_float4(a4, a5, a6, a7);
        }
        bcnt += GRID;
        gridbar(t, bcnt);

        // ---- gcomb: block owns cols [c0, c1); ALL threads compute (clamped), tail skips write ----
        {
            float V = 0.f;
            #pragma unroll 5
            for (int k = sub; k < GRID; k += 16)
                V += __ldcg(&d_ps[(size_t)k * MM + colc]);
            #pragma unroll
            for (int o = 8; o; o >>= 1) V += __shfl_xor_sync(0xffffffffu, V, o, 16);
            if (sub == 0 && cwrite) {
                V = fmaxf(V, 1e-37f);
                float g = d_logb[colc] - LN2F * lg2(V);
                d_g2[colc] = fmaf(g, LOG2EF, fgC);
                if (it == N_ITERS - 1) d_g[colc] = g;
            }
        }
        bcnt += GRID;
        gridbar(t, bcnt);
    }
}

// ---------------- final OT loss ----------------
__global__ __launch_bounds__(256) void k_ot() {
    int t = threadIdx.x;
    int j = blockIdx.x * 1024 + t * 4;
    int r0 = blockIdx.y * (NN / CHUNKS);
    float K2 = d_qK2, stepf = d_step, qB = d_qdqB, fgC = d_fgC;
    float4 gv = *(const float4*)(d_g + j);
    float base[4];
    base[0] = fmaf(gv.x, LOG2EF, fgC);
    base[1] = fmaf(gv.y, LOG2EF, fgC);
    base[2] = fmaf(gv.z, LOG2EF, fgC);
    base[3] = fmaf(gv.w, LOG2EF, fgC);
    const unsigned short* Cb = d_Cq + j;
    float acc = 0.f;
    for (int r = r0; r < r0 + (NN / CHUNKS); r++) {
        float frl2 = __ldg(&d_f[r]) * LOG2EF;
        uint2 v = *(const uint2*)(Cb + (size_t)r * MM);
        float qf[4] = {qf_lo(v.x), qf_hi(v.x), qf_lo(v.y), qf_hi(v.y)};
        #pragma unroll
        for (int c = 0; c < 4; c++) {
            float p = ex2(fmaf(qf[c], -K2, base[c] + frl2));
            float cd = fmaf(qf[c], stepf, qB);
            acc = fmaf(p, cd, acc);
        }
    }
    double da = (double)acc;
    #pragma unroll
    for (int o = 16; o; o >>= 1) da += __shfl_down_sync(0xffffffffu, da, o);
    __shared__ double sd[8];
    int lane = t & 31, w = t >> 5;
    if (lane == 0) sd[w] = da;
    __syncthreads();
    if (t == 0) {
        double tot = 0.0;
        #pragma unroll
        for (int k = 0; k < 8; k++) tot += sd[k];
        atomicAdd(&d_ot, tot);
    }
}

// ---------------- supervised alignment MSE ----------------
__global__ __launch_bounds__(128) void k_dist(const float* __restrict__ X,
                                              const float* __restrict__ W,
                                              const int* __restrict__ al) {
    int row = blockIdx.x, t = threadIdx.x;
    long long idx; int mask;
    if (d_is64) {
        long long v = ((const long long*)al)[row];
        mask = (v != -1LL);
        idx = v < 0 ? 0 : v;
    } else {
        int v = al[row];
        mask = (v != -1);
        idx = v < 0 ? 0 : (long long)v;
    }
    float4 a = ((const float4*)X)[(size_t)row * (DD / 4) + t];
    float4 b = ((const float4*)W)[(size_t)idx * (DD / 4) + t];
    float dx = a.x - b.x, dy = a.y - b.y, dz = a.z - b.z, dw = a.w - b.w;
    float s = dx * dx + dy * dy + dz * dz + dw * dw;
    #pragma unroll
    for (int o = 16; o; o >>= 1) s += __shfl_down_sync(0xffffffffu, s, o);
    __shared__ float red[4];
    if ((t & 31) == 0) red[t >> 5] = s;
    __syncthreads();
    if (t == 0) {
        float tot = red[0] + red[1] + red[2] + red[3];
        if (mask) {
            atomicAdd(&d_sq, (double)tot);
            atomicAdd(&d_cnt, 1.0);
        }
    }
}

// ---------------- finalize ----------------
__global__ void k_final(float* out) {
    double dl = (d_cnt > 0.0) ? d_sq / (d_cnt * (double)DD) : 0.0;
    out[0] = (float)(d_ot + dl);
}

// ---------------- launch ----------------
extern "C" void kernel_launch(void* const* d_in, const int* in_sizes, int n_in,
                              void* d_out, int out_size) {
    const float* X  = (const float*)d_in[0];
    const float* W  = (const float*)d_in[1];
    const int*   AL = (const int*)d_in[2];
    const float* T  = (const float*)d_in[3];
    float* out = (float*)d_out;

    k_init<<<1, 1024>>>(T, AL);
    k_sqnorm<<<NN, 128>>>(X, 0);
    k_sqnorm<<<MM, 128>>>(W, 1);
    k_scale<<<1, 1024>>>();
    dim3 gg(MM / 128, NN / 128);
    k_gemm<<<gg, 256>>>(X, W);
    k_ginit<<<MM / 256, 256>>>();

    k_loop<<<GRID, 1024>>>();

    k_ot<<<dim3(8, CHUNKS), 256>>>();
    k_dist<<<NN, 128>>>(X, W, AL);
    k_final<<<1, 1>>>(out);
}